// round 1
// baseline (speedup 1.0000x reference)
#include <cuda_runtime.h>
#include <cstdint>
#include <cstddef>

#define E 384
#define S 4096
#define BATCH 4
#define NROWS (BATCH * S)      // 16384
#define HID 1536
#define NH 6
#define HD 64

// ---------------- scratch (device globals — no runtime allocation) ----------
__device__ float g_mod[6 * BATCH * E];              // gamma1,beta1,alpha1,gamma2,beta2,alpha2
__device__ float g_ymod[(size_t)NROWS * E];
__device__ float g_q[(size_t)NROWS * E];
__device__ float g_k[(size_t)NROWS * E];
__device__ float g_v[(size_t)NROWS * E];
__device__ float g_att[(size_t)NROWS * E];
__device__ float g_y[(size_t)NROWS * E];
__device__ float g_zmod[(size_t)NROWS * E];
__device__ float g_h[(size_t)NROWS * HID];

// ---------------- cond projections: 6 x (4,384)@(384,384)+b ----------------
struct CondW { const float* w[6]; const float* b[6]; };

__global__ void cond_proj_k(const float* __restrict__ cond, CondW P,
                            float* __restrict__ mod) {
    int proj = blockIdx.x >> 2;
    int bb   = blockIdx.x & 3;
    __shared__ float cs[E];
    int t = threadIdx.x;
    cs[t] = cond[bb * E + t];
    __syncthreads();
    const float* W = P.w[proj];
    float acc = P.b[proj][t];
#pragma unroll 4
    for (int kk = 0; kk < E; ++kk) acc = fmaf(cs[kk], W[kk * E + t], acc);
    mod[(proj * BATCH + bb) * E + t] = acc;
}

// ---------------- LayerNorm + AdaLN modulate -------------------------------
__global__ void __launch_bounds__(128)
ln_mod_k(const float* __restrict__ in,
         const float* __restrict__ lnw, const float* __restrict__ lnb,
         const float* __restrict__ gamma, const float* __restrict__ beta,
         float* __restrict__ out) {
    int row = blockIdx.x, t = threadIdx.x;
    int bb = row >> 12;                    // row / 4096
    const float* xr = in + (size_t)row * E;
    float v0 = xr[t], v1 = xr[t + 128], v2 = xr[t + 256];
    float s  = v0 + v1 + v2;
    float sq = v0 * v0 + v1 * v1 + v2 * v2;
#pragma unroll
    for (int off = 16; off; off >>= 1) {
        s  += __shfl_xor_sync(0xffffffffu, s,  off);
        sq += __shfl_xor_sync(0xffffffffu, sq, off);
    }
    __shared__ float rs[4], rq[4];
    int w = t >> 5;
    if ((t & 31) == 0) { rs[w] = s; rq[w] = sq; }
    __syncthreads();
    s  = rs[0] + rs[1] + rs[2] + rs[3];
    sq = rq[0] + rq[1] + rq[2] + rq[3];
    float mean = s * (1.0f / E);
    float var  = sq * (1.0f / E) - mean * mean;
    float rstd = rsqrtf(var + 1e-5f);
    float* orow = out + (size_t)row * E;
    const float* g  = gamma + bb * E;
    const float* be = beta  + bb * E;
    float vv[3] = {v0, v1, v2};
#pragma unroll
    for (int i = 0; i < 3; ++i) {
        int e = t + i * 128;
        float val = (vv[i] - mean) * rstd * lnw[e] + lnb[e];
        // val*(1+g)+be
        orow[e] = fmaf(val, g[e], val + be[e]);
    }
}

// ---------------- generic tiled fp32 GEMM with fused epilogues -------------
// C[M,N] = A[M,K] @ W[K,N]  (+ epilogue)
// EPI 0: none    (qkv)
// EPI 1: C = res + C*alpha          (wo; alpha is [4][384])
// EPI 2: C = relu(C + bias)         (ff1)
// EPI 3: C = res + (C+bias)*alpha   (ff2 -> final output)
#define BM 128
#define BN 128
#define BK 8

template <int EPI>
__global__ void __launch_bounds__(256, 2)
gemm_k(const float* __restrict__ A, const float* __restrict__ W,
       const float* __restrict__ bias, const float* __restrict__ alpha,
       const float* __restrict__ res, float* __restrict__ C,
       int M, int N, int K) {
    __shared__ float As[BK][BM];
    __shared__ float Bs[BK][BN];

    int tid = threadIdx.x;
    int bm = blockIdx.y * BM;
    int bn = blockIdx.x * BN;

    // A tile load mapping: thread -> (row, k-quad)
    int ar = tid >> 1;
    int ak = (tid & 1) * 4;
    // B tile load mapping: thread -> (k-row, n-quad)
    int brow = tid >> 5;
    int bcol = (tid & 31) * 4;

    const float* Ap = A + (size_t)(bm + ar) * K + ak;
    const float* Wp = W + (size_t)brow * N + bn + bcol;

    float4 aReg = *(const float4*)Ap;
    float4 bReg = *(const float4*)Wp;

    float acc[8][8] = {};
    int tx = tid & 15, ty = tid >> 4;
    int m0 = ty * 8, n0 = tx * 8;

    int nk = K / BK;
    for (int kb = 0; kb < nk; ++kb) {
        As[ak + 0][ar] = aReg.x;
        As[ak + 1][ar] = aReg.y;
        As[ak + 2][ar] = aReg.z;
        As[ak + 3][ar] = aReg.w;
        *(float4*)&Bs[brow][bcol] = bReg;
        __syncthreads();
        if (kb + 1 < nk) {
            aReg = *(const float4*)(Ap + (size_t)(kb + 1) * BK);
            bReg = *(const float4*)(Wp + (size_t)(kb + 1) * BK * N);
        }
#pragma unroll
        for (int kk = 0; kk < BK; ++kk) {
            float4 a0 = *(const float4*)&As[kk][m0];
            float4 a1 = *(const float4*)&As[kk][m0 + 4];
            float4 b0 = *(const float4*)&Bs[kk][n0];
            float4 b1 = *(const float4*)&Bs[kk][n0 + 4];
            float av[8] = {a0.x, a0.y, a0.z, a0.w, a1.x, a1.y, a1.z, a1.w};
            float bv[8] = {b0.x, b0.y, b0.z, b0.w, b1.x, b1.y, b1.z, b1.w};
#pragma unroll
            for (int i = 0; i < 8; ++i)
#pragma unroll
                for (int j = 0; j < 8; ++j)
                    acc[i][j] = fmaf(av[i], bv[j], acc[i][j]);
        }
        __syncthreads();
    }

#pragma unroll
    for (int i = 0; i < 8; ++i) {
        int mrow = bm + m0 + i;
        int bIdx = mrow >> 12;
        size_t off = (size_t)mrow * N + bn + n0;
        float vals[8];
#pragma unroll
        for (int j = 0; j < 8; ++j) {
            float val = acc[i][j];
            int n = bn + n0 + j;
            if (EPI == 1) {
                val = res[off + j] + val * alpha[bIdx * E + n];
            } else if (EPI == 2) {
                val = fmaxf(val + bias[n], 0.0f);
            } else if (EPI == 3) {
                val = res[off + j] + (val + bias[n]) * alpha[bIdx * E + n];
            }
            vals[j] = val;
        }
        *(float4*)(C + off)     = make_float4(vals[0], vals[1], vals[2], vals[3]);
        *(float4*)(C + off + 4) = make_float4(vals[4], vals[5], vals[6], vals[7]);
    }
}

// ---------------- flash attention (fp32 SIMT, online softmax) --------------
// block = 512 threads = 16 warps, each warp owns one q row; 16 q rows share
// each staged K/V tile of 32 keys. grid = (S/16, B*NH)
__global__ void __launch_bounds__(512, 1)
attn_k(const float* __restrict__ q, const float* __restrict__ k,
       const float* __restrict__ v, float* __restrict__ out) {
    __shared__ float Ks[32 * 68];
    __shared__ float Vs[32 * 68];
    __shared__ float Ps[16][32];

    int tid = threadIdx.x;
    int lane = tid & 31, w = tid >> 5;
    int bh = blockIdx.y;
    int b = bh / NH, h = bh % NH;
    int qr = blockIdx.x * 16 + w;

    size_t rowbase = ((size_t)b * S + qr) * E + h * HD;
    float qreg[HD];
    const float* qp = q + rowbase;
#pragma unroll
    for (int d = 0; d < HD; ++d) qreg[d] = qp[d] * 0.125f;  // 1/sqrt(64)

    float m = -1e30f, l = 0.0f, o0 = 0.0f, o1 = 0.0f;

    // cooperative tile-load mapping: thread -> (key j, dim quad)
    int lj = tid >> 4;
    int ld = (tid & 15) * 4;
    size_t kvbase = ((size_t)b * S) * E + h * HD + ld;

    for (int kt = 0; kt < S / 32; ++kt) {
        __syncthreads();
        size_t g = kvbase + (size_t)(kt * 32 + lj) * E;
        float4 kk4 = *(const float4*)(k + g);
        float4 vv4 = *(const float4*)(v + g);
        *(float4*)&Ks[lj * 68 + ld] = kk4;
        *(float4*)&Vs[lj * 68 + ld] = vv4;
        __syncthreads();

        // score for this lane's key
        float sc = 0.0f;
        const float* kr = &Ks[lane * 68];
#pragma unroll
        for (int d = 0; d < HD; d += 4) {
            float4 kv = *(const float4*)(kr + d);
            sc = fmaf(qreg[d + 0], kv.x, sc);
            sc = fmaf(qreg[d + 1], kv.y, sc);
            sc = fmaf(qreg[d + 2], kv.z, sc);
            sc = fmaf(qreg[d + 3], kv.w, sc);
        }
        float mt = sc;
#pragma unroll
        for (int off = 16; off; off >>= 1)
            mt = fmaxf(mt, __shfl_xor_sync(0xffffffffu, mt, off));
        float mn = fmaxf(m, mt);
        float corr = __expf(m - mn);
        float p = __expf(sc - mn);
        float ls = p;
#pragma unroll
        for (int off = 16; off; off >>= 1)
            ls += __shfl_xor_sync(0xffffffffu, ls, off);
        l = l * corr + ls;
        o0 *= corr;
        o1 *= corr;
        Ps[w][lane] = p;
        __syncwarp();
#pragma unroll
        for (int jj = 0; jj < 32; ++jj) {
            float pv = Ps[w][jj];
            o0 = fmaf(pv, Vs[jj * 68 + lane], o0);
            o1 = fmaf(pv, Vs[jj * 68 + lane + 32], o1);
        }
        m = mn;
    }

    float inv = 1.0f / l;
    float* op = out + rowbase;
    op[lane] = o0 * inv;
    op[lane + 32] = o1 * inv;
}

// ---------------- launcher --------------------------------------------------
extern "C" void kernel_launch(void* const* d_in, const int* in_sizes, int n_in,
                              void* d_out, int out_size) {
    const float* x    = (const float*)d_in[0];
    const float* cond = (const float*)d_in[1];
    const float* ln1w = (const float*)d_in[14];
    const float* ln1b = (const float*)d_in[15];
    const float* ln2w = (const float*)d_in[16];
    const float* ln2b = (const float*)d_in[17];
    const float* wq   = (const float*)d_in[18];
    const float* wk   = (const float*)d_in[19];
    const float* wv   = (const float*)d_in[20];
    const float* wo   = (const float*)d_in[21];
    const float* ff1w = (const float*)d_in[22];
    const float* ff1b = (const float*)d_in[23];
    const float* ff2w = (const float*)d_in[24];
    const float* ff2b = (const float*)d_in[25];

    float *mod, *ymod, *q, *k, *v, *att, *y, *zmod, *hbuf;
    cudaGetSymbolAddress((void**)&mod,  g_mod);
    cudaGetSymbolAddress((void**)&ymod, g_ymod);
    cudaGetSymbolAddress((void**)&q,    g_q);
    cudaGetSymbolAddress((void**)&k,    g_k);
    cudaGetSymbolAddress((void**)&v,    g_v);
    cudaGetSymbolAddress((void**)&att,  g_att);
    cudaGetSymbolAddress((void**)&y,    g_y);
    cudaGetSymbolAddress((void**)&zmod, g_zmod);
    cudaGetSymbolAddress((void**)&hbuf, g_h);

    CondW P;
    P.w[0] = (const float*)d_in[2];  P.b[0] = (const float*)d_in[3];   // gamma1
    P.w[1] = (const float*)d_in[4];  P.b[1] = (const float*)d_in[5];   // beta1
    P.w[2] = (const float*)d_in[6];  P.b[2] = (const float*)d_in[7];   // alpha1
    P.w[3] = (const float*)d_in[8];  P.b[3] = (const float*)d_in[9];   // gamma2
    P.w[4] = (const float*)d_in[10]; P.b[4] = (const float*)d_in[11];  // beta2
    P.w[5] = (const float*)d_in[12]; P.b[5] = (const float*)d_in[13];  // alpha2

    const float* gamma1 = mod + 0 * BATCH * E;
    const float* beta1  = mod + 1 * BATCH * E;
    const float* alpha1 = mod + 2 * BATCH * E;
    const float* gamma2 = mod + 3 * BATCH * E;
    const float* beta2  = mod + 4 * BATCH * E;
    const float* alpha2 = mod + 5 * BATCH * E;

    // 1. AdaLN conditioning projections
    cond_proj_k<<<24, E>>>(cond, P, mod);

    // 2. LN1 + modulate
    ln_mod_k<<<NROWS, 128>>>(x, ln1w, ln1b, gamma1, beta1, ymod);

    // 3. QKV projections
    dim3 gE(E / BN, NROWS / BM);
    gemm_k<0><<<gE, 256>>>(ymod, wq, nullptr, nullptr, nullptr, q, NROWS, E, E);
    gemm_k<0><<<gE, 256>>>(ymod, wk, nullptr, nullptr, nullptr, k, NROWS, E, E);
    gemm_k<0><<<gE, 256>>>(ymod, wv, nullptr, nullptr, nullptr, v, NROWS, E, E);

    // 4. attention
    attn_k<<<dim3(S / 16, BATCH * NH), 512>>>(q, k, v, att);

    // 5. wo + alpha1 scale + residual  -> y
    gemm_k<1><<<gE, 256>>>(att, wo, nullptr, alpha1, x, y, NROWS, E, E);

    // 6. LN2 + modulate
    ln_mod_k<<<NROWS, 128>>>(y, ln2w, ln2b, gamma2, beta2, zmod);

    // 7. FF1 + bias + relu
    dim3 gH(HID / BN, NROWS / BM);
    gemm_k<2><<<gH, 256>>>(zmod, ff1w, ff1b, nullptr, nullptr, hbuf, NROWS, HID, E);

    // 8. FF2 + bias, * alpha2, + y  -> final output
    gemm_k<3><<<gE, 256>>>(hbuf, ff2w, ff2b, alpha2, y, (float*)d_out, NROWS, E, HID);
}

// round 2
// speedup vs baseline: 5.3271x; 5.3271x over previous
#include <cuda_runtime.h>
#include <cuda_bf16.h>
#include <cstdint>
#include <cstddef>

#define E 384
#define S 4096
#define BATCH 4
#define NROWS (BATCH * S)      // 16384
#define HID 1536
#define NH 6
#define HD 64

// ---------------- scratch (device globals — no runtime allocation) ----------
__device__ float g_mod[6 * BATCH * E];
__device__ float g_ymod[(size_t)NROWS * E];
__device__ __nv_bfloat16 g_q[(size_t)NROWS * E];
__device__ __nv_bfloat16 g_k[(size_t)NROWS * E];
__device__ __nv_bfloat16 g_v[(size_t)NROWS * E];
__device__ float g_att[(size_t)NROWS * E];
__device__ float g_y[(size_t)NROWS * E];
__device__ float g_zmod[(size_t)NROWS * E];
__device__ float g_h[(size_t)NROWS * HID];

// ---------------- small helpers --------------------------------------------
__device__ __forceinline__ uint32_t sptr(const void* p) {
    return (uint32_t)__cvta_generic_to_shared(p);
}
__device__ __forceinline__ void ldsm_x4(uint32_t* r, uint32_t addr) {
    asm volatile("ldmatrix.sync.aligned.m8n8.x4.shared.b16 {%0,%1,%2,%3}, [%4];"
                 : "=r"(r[0]), "=r"(r[1]), "=r"(r[2]), "=r"(r[3]) : "r"(addr));
}
__device__ __forceinline__ void ldsm_x4_t(uint32_t* r, uint32_t addr) {
    asm volatile("ldmatrix.sync.aligned.m8n8.x4.trans.shared.b16 {%0,%1,%2,%3}, [%4];"
                 : "=r"(r[0]), "=r"(r[1]), "=r"(r[2]), "=r"(r[3]) : "r"(addr));
}
__device__ __forceinline__ void mma_bf16(float* c, const uint32_t* a,
                                         uint32_t b0, uint32_t b1) {
    asm volatile(
        "mma.sync.aligned.m16n8k16.row.col.f32.bf16.bf16.f32 "
        "{%0,%1,%2,%3}, {%4,%5,%6,%7}, {%8,%9}, {%0,%1,%2,%3};"
        : "+f"(c[0]), "+f"(c[1]), "+f"(c[2]), "+f"(c[3])
        : "r"(a[0]), "r"(a[1]), "r"(a[2]), "r"(a[3]), "r"(b0), "r"(b1));
}
__device__ __forceinline__ uint32_t pack_bf16(float lo, float hi) {
    __nv_bfloat162 h2 = __floats2bfloat162_rn(lo, hi);
    return *reinterpret_cast<uint32_t*>(&h2);
}

// ---------------- cond projections ------------------------------------------
struct CondW { const float* w[6]; const float* b[6]; };

__global__ void cond_proj_k(const float* __restrict__ cond, CondW P,
                            float* __restrict__ mod) {
    int proj = blockIdx.x >> 2;
    int bb   = blockIdx.x & 3;
    __shared__ float cs[E];
    int t = threadIdx.x;
    cs[t] = cond[bb * E + t];
    __syncthreads();
    const float* W = P.w[proj];
    float acc = P.b[proj][t];
#pragma unroll 4
    for (int kk = 0; kk < E; ++kk) acc = fmaf(cs[kk], W[kk * E + t], acc);
    mod[(proj * BATCH + bb) * E + t] = acc;
}

// ---------------- LayerNorm + AdaLN modulate --------------------------------
__global__ void __launch_bounds__(128)
ln_mod_k(const float* __restrict__ in,
         const float* __restrict__ lnw, const float* __restrict__ lnb,
         const float* __restrict__ gamma, const float* __restrict__ beta,
         float* __restrict__ out) {
    int row = blockIdx.x, t = threadIdx.x;
    int bb = row >> 12;
    const float* xr = in + (size_t)row * E;
    float v0 = xr[t], v1 = xr[t + 128], v2 = xr[t + 256];
    float s  = v0 + v1 + v2;
    float sq = v0 * v0 + v1 * v1 + v2 * v2;
#pragma unroll
    for (int off = 16; off; off >>= 1) {
        s  += __shfl_xor_sync(0xffffffffu, s,  off);
        sq += __shfl_xor_sync(0xffffffffu, sq, off);
    }
    __shared__ float rs[4], rq[4];
    int w = t >> 5;
    if ((t & 31) == 0) { rs[w] = s; rq[w] = sq; }
    __syncthreads();
    s  = rs[0] + rs[1] + rs[2] + rs[3];
    sq = rq[0] + rq[1] + rq[2] + rq[3];
    float mean = s * (1.0f / E);
    float var  = sq * (1.0f / E) - mean * mean;
    float rstd = rsqrtf(var + 1e-5f);
    float* orow = out + (size_t)row * E;
    const float* g  = gamma + bb * E;
    const float* be = beta  + bb * E;
    float vv[3] = {v0, v1, v2};
#pragma unroll
    for (int i = 0; i < 3; ++i) {
        int e = t + i * 128;
        float val = (vv[i] - mean) * rstd * lnw[e] + lnb[e];
        orow[e] = fmaf(val, g[e], val + be[e]);
    }
}

// ---------------- generic tiled fp32 GEMM with fused epilogues -------------
// EPI 0: none (f32 out)
// EPI 1: C = res + C*alpha          (wo)
// EPI 2: C = relu(C + bias)         (ff1)
// EPI 3: C = res + (C+bias)*alpha   (ff2 -> final output)
// EPI 4: C = bf16(C * scale)        (qkv)
#define BM 128
#define BN 128
#define BK 8

template <int EPI>
__global__ void __launch_bounds__(256, 2)
gemm_k(const float* __restrict__ A, const float* __restrict__ W,
       const float* __restrict__ bias, const float* __restrict__ alpha,
       const float* __restrict__ res, void* __restrict__ Cv,
       int M, int N, int K, float scale) {
    __shared__ float As[BK][BM];
    __shared__ float Bs[BK][BN];

    int tid = threadIdx.x;
    int bm = blockIdx.y * BM;
    int bn = blockIdx.x * BN;

    int ar = tid >> 1;
    int ak = (tid & 1) * 4;
    int brow = tid >> 5;
    int bcol = (tid & 31) * 4;

    const float* Ap = A + (size_t)(bm + ar) * K + ak;
    const float* Wp = W + (size_t)brow * N + bn + bcol;

    float4 aReg = *(const float4*)Ap;
    float4 bReg = *(const float4*)Wp;

    float acc[8][8] = {};
    int tx = tid & 15, ty = tid >> 4;
    int m0 = ty * 8, n0 = tx * 8;

    int nk = K / BK;
    for (int kb = 0; kb < nk; ++kb) {
        As[ak + 0][ar] = aReg.x;
        As[ak + 1][ar] = aReg.y;
        As[ak + 2][ar] = aReg.z;
        As[ak + 3][ar] = aReg.w;
        *(float4*)&Bs[brow][bcol] = bReg;
        __syncthreads();
        if (kb + 1 < nk) {
            aReg = *(const float4*)(Ap + (size_t)(kb + 1) * BK);
            bReg = *(const float4*)(Wp + (size_t)(kb + 1) * BK * N);
        }
#pragma unroll
        for (int kk = 0; kk < BK; ++kk) {
            float4 a0 = *(const float4*)&As[kk][m0];
            float4 a1 = *(const float4*)&As[kk][m0 + 4];
            float4 b0 = *(const float4*)&Bs[kk][n0];
            float4 b1 = *(const float4*)&Bs[kk][n0 + 4];
            float av[8] = {a0.x, a0.y, a0.z, a0.w, a1.x, a1.y, a1.z, a1.w};
            float bv[8] = {b0.x, b0.y, b0.z, b0.w, b1.x, b1.y, b1.z, b1.w};
#pragma unroll
            for (int i = 0; i < 8; ++i)
#pragma unroll
                for (int j = 0; j < 8; ++j)
                    acc[i][j] = fmaf(av[i], bv[j], acc[i][j]);
        }
        __syncthreads();
    }

#pragma unroll
    for (int i = 0; i < 8; ++i) {
        int mrow = bm + m0 + i;
        int bIdx = mrow >> 12;
        size_t off = (size_t)mrow * N + bn + n0;
        if (EPI == 4) {
            __nv_bfloat16* Cb = (__nv_bfloat16*)Cv;
            uint32_t pk[4];
#pragma unroll
            for (int jj = 0; jj < 4; ++jj)
                pk[jj] = pack_bf16(acc[i][2 * jj] * scale, acc[i][2 * jj + 1] * scale);
            *(uint4*)(Cb + off) = *(uint4*)pk;
        } else {
            float* C = (float*)Cv;
            float vals[8];
#pragma unroll
            for (int j = 0; j < 8; ++j) {
                float val = acc[i][j];
                int n = bn + n0 + j;
                if (EPI == 1) {
                    val = res[off + j] + val * alpha[bIdx * E + n];
                } else if (EPI == 2) {
                    val = fmaxf(val + bias[n], 0.0f);
                } else if (EPI == 3) {
                    val = res[off + j] + (val + bias[n]) * alpha[bIdx * E + n];
                }
                vals[j] = val;
            }
            *(float4*)(C + off)     = make_float4(vals[0], vals[1], vals[2], vals[3]);
            *(float4*)(C + off + 4) = make_float4(vals[4], vals[5], vals[6], vals[7]);
        }
    }
}

// ---------------- flash attention v2, bf16 mma.sync -------------------------
// block = 128 threads (4 warps). Q tile 64 rows (16/warp), KV tiles of 64 keys.
// grid = (S/64, B*NH). Smem rows padded to 72 bf16 -> conflict-free ldmatrix.
#define KSTRIDE 72

__global__ void __launch_bounds__(128)
attn_mma_k(const __nv_bfloat16* __restrict__ q,
           const __nv_bfloat16* __restrict__ k,
           const __nv_bfloat16* __restrict__ v,
           float* __restrict__ out) {
    __shared__ __nv_bfloat16 Ks[64 * KSTRIDE];
    __shared__ __nv_bfloat16 Vs[64 * KSTRIDE];

    const int tid = threadIdx.x;
    const int lane = tid & 31, w = tid >> 5;
    const int bh = blockIdx.y;
    const int b = bh / NH, h = bh % NH;
    const int q0 = blockIdx.x * 64;

    // cooperative tile-load mapping
    const int cg = tid & 7;          // col group (8 bf16 each)
    const int r16 = tid >> 3;        // row 0..15 per pass

    // ---- stage Q tile into Ks, ldmatrix to registers ----
    {
        size_t gbase = ((size_t)(b * S + q0 + r16)) * E + h * HD + cg * 8;
#pragma unroll
        for (int p = 0; p < 4; ++p) {
            *(uint4*)&Ks[(r16 + p * 16) * KSTRIDE + cg * 8] =
                *(const uint4*)(q + gbase + (size_t)p * 16 * E);
        }
    }
    __syncthreads();

    uint32_t a_q[4][4];
    {
        int lrow = lane & 15, lcol = (lane >> 4) * 8;
        int m0 = w * 16;
#pragma unroll
        for (int kc = 0; kc < 4; ++kc)
            ldsm_x4(a_q[kc], sptr(&Ks[(m0 + lrow) * KSTRIDE + kc * 16 + lcol]));
    }

    float mr0 = -1e30f, mr1 = -1e30f, l0 = 0.0f, l1 = 0.0f;
    float o[8][4] = {};

    // B-fragment lane mappings
    const int kb_row = (lane & 7) + ((lane & 16) ? 8 : 0);   // QK^T (non-trans)
    const int kb_col = (lane & 8) ? 8 : 0;
    const int vb_row = (lane & 7) + ((lane & 8) ? 8 : 0);    // PV (trans)
    const int vb_col = (lane & 16) ? 8 : 0;

    const size_t kvg0 = ((size_t)(b * S + r16)) * E + h * HD + cg * 8;

    for (int kt = 0; kt < S / 64; ++kt) {
        __syncthreads();
        // load K/V tiles (bf16 already)
        size_t gb = kvg0 + (size_t)kt * 64 * E;
#pragma unroll
        for (int p = 0; p < 4; ++p) {
            int row = r16 + p * 16;
            *(uint4*)&Ks[row * KSTRIDE + cg * 8] = *(const uint4*)(k + gb + (size_t)p * 16 * E);
            *(uint4*)&Vs[row * KSTRIDE + cg * 8] = *(const uint4*)(v + gb + (size_t)p * 16 * E);
        }
        __syncthreads();

        // ---- S = Q K^T ----
        float s[8][4] = {};
#pragma unroll
        for (int kc = 0; kc < 4; ++kc) {
#pragma unroll
            for (int nb2 = 0; nb2 < 4; ++nb2) {
                uint32_t bb[4];
                ldsm_x4(bb, sptr(&Ks[(nb2 * 16 + kb_row) * KSTRIDE + kc * 16 + kb_col]));
                mma_bf16(s[nb2 * 2],     a_q[kc], bb[0], bb[1]);
                mma_bf16(s[nb2 * 2 + 1], a_q[kc], bb[2], bb[3]);
            }
        }

        // ---- online softmax ----
        float mx0 = -1e30f, mx1 = -1e30f;
#pragma unroll
        for (int j = 0; j < 8; ++j) {
            mx0 = fmaxf(mx0, fmaxf(s[j][0], s[j][1]));
            mx1 = fmaxf(mx1, fmaxf(s[j][2], s[j][3]));
        }
        mx0 = fmaxf(mx0, __shfl_xor_sync(0xffffffffu, mx0, 1));
        mx0 = fmaxf(mx0, __shfl_xor_sync(0xffffffffu, mx0, 2));
        mx1 = fmaxf(mx1, __shfl_xor_sync(0xffffffffu, mx1, 1));
        mx1 = fmaxf(mx1, __shfl_xor_sync(0xffffffffu, mx1, 2));
        float mn0 = fmaxf(mr0, mx0), mn1 = fmaxf(mr1, mx1);
        float c0 = __expf(mr0 - mn0), c1 = __expf(mr1 - mn1);

        uint32_t pA[8], pB[8];
        float sum0 = 0.0f, sum1 = 0.0f;
#pragma unroll
        for (int j = 0; j < 8; ++j) {
            float p00 = __expf(s[j][0] - mn0);
            float p01 = __expf(s[j][1] - mn0);
            float p10 = __expf(s[j][2] - mn1);
            float p11 = __expf(s[j][3] - mn1);
            sum0 += p00 + p01;
            sum1 += p10 + p11;
            pA[j] = pack_bf16(p00, p01);
            pB[j] = pack_bf16(p10, p11);
        }
        sum0 += __shfl_xor_sync(0xffffffffu, sum0, 1);
        sum0 += __shfl_xor_sync(0xffffffffu, sum0, 2);
        sum1 += __shfl_xor_sync(0xffffffffu, sum1, 1);
        sum1 += __shfl_xor_sync(0xffffffffu, sum1, 2);
        l0 = l0 * c0 + sum0;
        l1 = l1 * c1 + sum1;
#pragma unroll
        for (int j = 0; j < 8; ++j) {
            o[j][0] *= c0; o[j][1] *= c0;
            o[j][2] *= c1; o[j][3] *= c1;
        }
        mr0 = mn0; mr1 = mn1;

        // ---- O += P V ----
#pragma unroll
        for (int kc = 0; kc < 4; ++kc) {
            uint32_t ap[4] = {pA[2 * kc], pB[2 * kc], pA[2 * kc + 1], pB[2 * kc + 1]};
#pragma unroll
            for (int nb2 = 0; nb2 < 4; ++nb2) {
                uint32_t bb[4];
                ldsm_x4_t(bb, sptr(&Vs[(kc * 16 + vb_row) * KSTRIDE + nb2 * 16 + vb_col]));
                mma_bf16(o[nb2 * 2],     ap, bb[0], bb[1]);
                mma_bf16(o[nb2 * 2 + 1], ap, bb[2], bb[3]);
            }
        }
    }

    // ---- epilogue ----
    float i0 = 1.0f / l0, i1 = 1.0f / l1;
    int row0 = q0 + w * 16 + (lane >> 2);
    int colb = h * HD + (lane & 3) * 2;
    float* out0 = out + ((size_t)(b * S + row0)) * E + colb;
    float* out1 = out0 + 8 * (size_t)E;
#pragma unroll
    for (int j = 0; j < 8; ++j) {
        *(float2*)(out0 + j * 8) = make_float2(o[j][0] * i0, o[j][1] * i0);
        *(float2*)(out1 + j * 8) = make_float2(o[j][2] * i1, o[j][3] * i1);
    }
}

// ---------------- launcher ---------------------------------------------------
extern "C" void kernel_launch(void* const* d_in, const int* in_sizes, int n_in,
                              void* d_out, int out_size) {
    const float* x    = (const float*)d_in[0];
    const float* cond = (const float*)d_in[1];
    const float* ln1w = (const float*)d_in[14];
    const float* ln1b = (const float*)d_in[15];
    const float* ln2w = (const float*)d_in[16];
    const float* ln2b = (const float*)d_in[17];
    const float* wq   = (const float*)d_in[18];
    const float* wk   = (const float*)d_in[19];
    const float* wv   = (const float*)d_in[20];
    const float* wo   = (const float*)d_in[21];
    const float* ff1w = (const float*)d_in[22];
    const float* ff1b = (const float*)d_in[23];
    const float* ff2w = (const float*)d_in[24];
    const float* ff2b = (const float*)d_in[25];

    float *mod, *ymod, *att, *y, *zmod, *hbuf;
    __nv_bfloat16 *qb, *kb, *vb;
    cudaGetSymbolAddress((void**)&mod,  g_mod);
    cudaGetSymbolAddress((void**)&ymod, g_ymod);
    cudaGetSymbolAddress((void**)&qb,   g_q);
    cudaGetSymbolAddress((void**)&kb,   g_k);
    cudaGetSymbolAddress((void**)&vb,   g_v);
    cudaGetSymbolAddress((void**)&att,  g_att);
    cudaGetSymbolAddress((void**)&y,    g_y);
    cudaGetSymbolAddress((void**)&zmod, g_zmod);
    cudaGetSymbolAddress((void**)&hbuf, g_h);

    CondW P;
    P.w[0] = (const float*)d_in[2];  P.b[0] = (const float*)d_in[3];
    P.w[1] = (const float*)d_in[4];  P.b[1] = (const float*)d_in[5];
    P.w[2] = (const float*)d_in[6];  P.b[2] = (const float*)d_in[7];
    P.w[3] = (const float*)d_in[8];  P.b[3] = (const float*)d_in[9];
    P.w[4] = (const float*)d_in[10]; P.b[4] = (const float*)d_in[11];
    P.w[5] = (const float*)d_in[12]; P.b[5] = (const float*)d_in[13];

    const float* gamma1 = mod + 0 * BATCH * E;
    const float* beta1  = mod + 1 * BATCH * E;
    const float* alpha1 = mod + 2 * BATCH * E;
    const float* gamma2 = mod + 3 * BATCH * E;
    const float* beta2  = mod + 4 * BATCH * E;
    const float* alpha2 = mod + 5 * BATCH * E;

    cond_proj_k<<<24, E>>>(cond, P, mod);
    ln_mod_k<<<NROWS, 128>>>(x, ln1w, ln1b, gamma1, beta1, ymod);

    dim3 gE(E / BN, NROWS / BM);
    gemm_k<4><<<gE, 256>>>(ymod, wq, nullptr, nullptr, nullptr, qb, NROWS, E, E, 0.125f);
    gemm_k<4><<<gE, 256>>>(ymod, wk, nullptr, nullptr, nullptr, kb, NROWS, E, E, 1.0f);
    gemm_k<4><<<gE, 256>>>(ymod, wv, nullptr, nullptr, nullptr, vb, NROWS, E, E, 1.0f);

    attn_mma_k<<<dim3(S / 64, BATCH * NH), 128>>>(qb, kb, vb, att);

    gemm_k<1><<<gE, 256>>>(att, wo, nullptr, alpha1, x, y, NROWS, E, E, 1.0f);
    ln_mod_k<<<NROWS, 128>>>(y, ln2w, ln2b, gamma2, beta2, zmod);

    dim3 gH(HID / BN, NROWS / BM);
    gemm_k<2><<<gH, 256>>>(zmod, ff1w, ff1b, nullptr, nullptr, hbuf, NROWS, HID, E, 1.0f);
    gemm_k<3><<<gE, 256>>>(hbuf, ff2w, ff2b, alpha2, y, d_out, NROWS, E, HID, 1.0f);
}

// round 3
// speedup vs baseline: 12.9117x; 2.4238x over previous
#include <cuda_runtime.h>
#include <cuda_bf16.h>
#include <cstdint>
#include <cstddef>

#define E 384
#define S 4096
#define BATCH 4
#define NROWS (BATCH * S)      // 16384
#define HID 1536
#define NH 6
#define HD 64

typedef __nv_bfloat16 bf16;

// ---------------- scratch (device globals — no runtime allocation) ----------
__device__ float g_mod[6 * BATCH * E];
__device__ bf16  g_ymod[(size_t)NROWS * E];
__device__ bf16  g_zmod[(size_t)NROWS * E];
__device__ bf16  g_q[(size_t)NROWS * E];
__device__ bf16  g_k[(size_t)NROWS * E];
__device__ bf16  g_v[(size_t)NROWS * E];
__device__ bf16  g_att[(size_t)NROWS * E];
__device__ bf16  g_h[(size_t)NROWS * HID];
__device__ float g_y[(size_t)NROWS * E];
// bf16 weight copies
__device__ bf16 g_wq[E * E];
__device__ bf16 g_wk[E * E];
__device__ bf16 g_wv[E * E];
__device__ bf16 g_wo[E * E];
__device__ bf16 g_ff1[E * HID];
__device__ bf16 g_ff2[HID * E];

// ---------------- small helpers --------------------------------------------
__device__ __forceinline__ uint32_t sptr(const void* p) {
    return (uint32_t)__cvta_generic_to_shared(p);
}
__device__ __forceinline__ void ldsm_x4(uint32_t* r, uint32_t addr) {
    asm volatile("ldmatrix.sync.aligned.m8n8.x4.shared.b16 {%0,%1,%2,%3}, [%4];"
                 : "=r"(r[0]), "=r"(r[1]), "=r"(r[2]), "=r"(r[3]) : "r"(addr));
}
__device__ __forceinline__ void ldsm_x4_t(uint32_t* r, uint32_t addr) {
    asm volatile("ldmatrix.sync.aligned.m8n8.x4.trans.shared.b16 {%0,%1,%2,%3}, [%4];"
                 : "=r"(r[0]), "=r"(r[1]), "=r"(r[2]), "=r"(r[3]) : "r"(addr));
}
__device__ __forceinline__ void mma_bf16(float* c, const uint32_t* a,
                                         uint32_t b0, uint32_t b1) {
    asm volatile(
        "mma.sync.aligned.m16n8k16.row.col.f32.bf16.bf16.f32 "
        "{%0,%1,%2,%3}, {%4,%5,%6,%7}, {%8,%9}, {%0,%1,%2,%3};"
        : "+f"(c[0]), "+f"(c[1]), "+f"(c[2]), "+f"(c[3])
        : "r"(a[0]), "r"(a[1]), "r"(a[2]), "r"(a[3]), "r"(b0), "r"(b1));
}
__device__ __forceinline__ uint32_t pack_bf16(float lo, float hi) {
    __nv_bfloat162 h2 = __floats2bfloat162_rn(lo, hi);
    return *reinterpret_cast<uint32_t*>(&h2);
}

// ---------------- fp32 -> bf16 conversion ----------------------------------
__global__ void f2b_k(const float* __restrict__ src, bf16* __restrict__ dst, int n4) {
    int i = blockIdx.x * 256 + threadIdx.x;
    if (i < n4) {
        float4 v = ((const float4*)src)[i];
        uint32_t pk[2] = {pack_bf16(v.x, v.y), pack_bf16(v.z, v.w)};
        ((uint2*)dst)[i] = *(uint2*)pk;
    }
}

// ---------------- cond projections ------------------------------------------
struct CondW { const float* w[6]; const float* b[6]; };

__global__ void cond_proj_k(const float* __restrict__ cond, CondW P,
                            float* __restrict__ mod) {
    int proj = blockIdx.x >> 2;
    int bb   = blockIdx.x & 3;
    __shared__ float cs[E];
    int t = threadIdx.x;
    cs[t] = cond[bb * E + t];
    __syncthreads();
    const float* W = P.w[proj];
    float acc = P.b[proj][t];
#pragma unroll 4
    for (int kk = 0; kk < E; ++kk) acc = fmaf(cs[kk], W[kk * E + t], acc);
    mod[(proj * BATCH + bb) * E + t] = acc;
}

// ---------------- LayerNorm + AdaLN modulate (bf16 out) ---------------------
__global__ void __launch_bounds__(128)
ln_mod_k(const float* __restrict__ in,
         const float* __restrict__ lnw, const float* __restrict__ lnb,
         const float* __restrict__ gamma, const float* __restrict__ beta,
         bf16* __restrict__ out) {
    int row = blockIdx.x, t = threadIdx.x;
    int bb = row >> 12;
    const float* xr = in + (size_t)row * E;
    float v0 = xr[t], v1 = xr[t + 128], v2 = xr[t + 256];
    float s  = v0 + v1 + v2;
    float sq = v0 * v0 + v1 * v1 + v2 * v2;
#pragma unroll
    for (int off = 16; off; off >>= 1) {
        s  += __shfl_xor_sync(0xffffffffu, s,  off);
        sq += __shfl_xor_sync(0xffffffffu, sq, off);
    }
    __shared__ float rs[4], rq[4];
    int w = t >> 5;
    if ((t & 31) == 0) { rs[w] = s; rq[w] = sq; }
    __syncthreads();
    s  = rs[0] + rs[1] + rs[2] + rs[3];
    sq = rq[0] + rq[1] + rq[2] + rq[3];
    float mean = s * (1.0f / E);
    float var  = sq * (1.0f / E) - mean * mean;
    float rstd = rsqrtf(var + 1e-5f);
    bf16* orow = out + (size_t)row * E;
    const float* g  = gamma + bb * E;
    const float* be = beta  + bb * E;
    float vv[3] = {v0, v1, v2};
#pragma unroll
    for (int i = 0; i < 3; ++i) {
        int e = t + i * 128;
        float val = (vv[i] - mean) * rstd * lnw[e] + lnb[e];
        orow[e] = __float2bfloat16(fmaf(val, g[e], val + be[e]));
    }
}

// ---------------- bf16 tensor-core GEMM with fused epilogues ----------------
// C[M,N] = A[M,K](bf16) @ W[K,N](bf16)
// EPI 0: bf16 out, *scale (qkv; gridDim.z selects wq/wk/wv)
// EPI 1: f32 out, res + C*alpha            (wo)
// EPI 2: bf16 out, relu(C + bias)          (ff1)
// EPI 3: f32 out, res + (C+bias)*alpha     (ff2 -> final)
#define ASTR 40
#define BSTR 136

template <int EPI>
__global__ void __launch_bounds__(256, 2)
gemm_bf16_k(const bf16* __restrict__ A, const bf16* __restrict__ W,
            const float* __restrict__ bias, const float* __restrict__ alpha,
            const float* __restrict__ res, void* __restrict__ Cv,
            int M, int N, int K, float scale,
            const bf16* W2, const bf16* W3, void* C2, void* C3) {
    __shared__ bf16 As[128 * ASTR];
    __shared__ bf16 Bs[32 * BSTR];

    if (EPI == 0) {
        int z = blockIdx.z;
        if (z == 1) { W = W2; Cv = C2; scale = 1.0f; }
        else if (z == 2) { W = W3; Cv = C3; scale = 1.0f; }
    }

    const int tid = threadIdx.x;
    const int lane = tid & 31, wid = tid >> 5;
    const int bm = blockIdx.y * 128;
    const int bn = blockIdx.x * 128;
    const int warp_m = wid >> 2, warp_n = wid & 3;

    // global load mappings
    const int arow = tid >> 1, acol = (tid & 1) * 16;
    const int brow = tid >> 3, bcol = (tid & 7) * 16;
    const bf16* Ap = A + (size_t)(bm + arow) * K + acol;
    const bf16* Wp = W + (size_t)brow * N + bn + bcol;

    uint4 a0 = *(const uint4*)Ap,       a1 = *(const uint4*)(Ap + 8);
    uint4 b0 = *(const uint4*)Wp,       b1 = *(const uint4*)(Wp + 8);

    float acc[4][4][4] = {};

    const int lrow = lane & 15, lcol = (lane >> 4) * 8;
    const int tb_row = (lane & 7) + ((lane & 8) ? 8 : 0);
    const int tb_col = (lane & 16) ? 8 : 0;

    const int nk = K / 32;
    for (int kb = 0; kb < nk; ++kb) {
        *(uint4*)&As[arow * ASTR + acol]     = a0;
        *(uint4*)&As[arow * ASTR + acol + 8] = a1;
        *(uint4*)&Bs[brow * BSTR + bcol]     = b0;
        *(uint4*)&Bs[brow * BSTR + bcol + 8] = b1;
        __syncthreads();
        if (kb + 1 < nk) {
            const bf16* Apn = Ap + (size_t)(kb + 1) * 32;
            const bf16* Wpn = Wp + (size_t)(kb + 1) * 32 * N;
            a0 = *(const uint4*)Apn; a1 = *(const uint4*)(Apn + 8);
            b0 = *(const uint4*)Wpn; b1 = *(const uint4*)(Wpn + 8);
        }
#pragma unroll
        for (int ks = 0; ks < 2; ++ks) {
            uint32_t af[4][4];
#pragma unroll
            for (int mi = 0; mi < 4; ++mi)
                ldsm_x4(af[mi], sptr(&As[(warp_m * 64 + mi * 16 + lrow) * ASTR + ks * 16 + lcol]));
            uint32_t bf_[2][4];
#pragma unroll
            for (int ni2 = 0; ni2 < 2; ++ni2)
                ldsm_x4_t(bf_[ni2], sptr(&Bs[(ks * 16 + tb_row) * BSTR + warp_n * 32 + ni2 * 16 + tb_col]));
#pragma unroll
            for (int mi = 0; mi < 4; ++mi) {
#pragma unroll
                for (int ni2 = 0; ni2 < 2; ++ni2) {
                    mma_bf16(acc[mi][ni2 * 2],     af[mi], bf_[ni2][0], bf_[ni2][1]);
                    mma_bf16(acc[mi][ni2 * 2 + 1], af[mi], bf_[ni2][2], bf_[ni2][3]);
                }
            }
        }
        __syncthreads();
    }

    // epilogue
#pragma unroll
    for (int mi = 0; mi < 4; ++mi) {
#pragma unroll
        for (int rr = 0; rr < 2; ++rr) {
            int row = bm + warp_m * 64 + mi * 16 + (lane >> 2) + rr * 8;
            int bIdx = row >> 12;
            size_t rowoff = (size_t)row * N;
#pragma unroll
            for (int ni = 0; ni < 4; ++ni) {
                int col = bn + warp_n * 32 + ni * 8 + (lane & 3) * 2;
                float c0 = acc[mi][ni][rr * 2], c1 = acc[mi][ni][rr * 2 + 1];
                if (EPI == 0) {
                    uint32_t pk = pack_bf16(c0 * scale, c1 * scale);
                    *(uint32_t*)((bf16*)Cv + rowoff + col) = pk;
                } else if (EPI == 2) {
                    float t0 = fmaxf(c0 + bias[col], 0.0f);
                    float t1 = fmaxf(c1 + bias[col + 1], 0.0f);
                    uint32_t pk = pack_bf16(t0, t1);
                    *(uint32_t*)((bf16*)Cv + rowoff + col) = pk;
                } else if (EPI == 1) {
                    float2 r = *(const float2*)(res + rowoff + col);
                    float a0f = alpha[bIdx * E + col], a1f = alpha[bIdx * E + col + 1];
                    *(float2*)((float*)Cv + rowoff + col) =
                        make_float2(r.x + c0 * a0f, r.y + c1 * a1f);
                } else {  // EPI == 3
                    float2 r = *(const float2*)(res + rowoff + col);
                    float a0f = alpha[bIdx * E + col], a1f = alpha[bIdx * E + col + 1];
                    *(float2*)((float*)Cv + rowoff + col) =
                        make_float2(r.x + (c0 + bias[col]) * a0f,
                                    r.y + (c1 + bias[col + 1]) * a1f);
                }
            }
        }
    }
}

// ---------------- flash attention v2, bf16 mma.sync, 8 warps ----------------
// block = 256 threads (8 warps), Q tile 128 rows (16/warp), KV tiles 64 keys.
// grid = (S/128, B*NH). bf16 output.
#define KSTRIDE 72

__global__ void __launch_bounds__(256)
attn_mma_k(const bf16* __restrict__ q, const bf16* __restrict__ k,
           const bf16* __restrict__ v, bf16* __restrict__ out) {
    __shared__ bf16 Ks[64 * KSTRIDE];
    __shared__ bf16 Vs[64 * KSTRIDE];

    const int tid = threadIdx.x;
    const int lane = tid & 31, w = tid >> 5;
    const int bh = blockIdx.y;
    const int b = bh / NH, h = bh % NH;
    const int q0 = blockIdx.x * 128;

    const int cg8 = (tid & 7) * 8;     // 8-bf16 column group
    const int r32 = tid >> 3;          // 0..31

    // ---- stage Q tile (128 rows) through Ks/Vs, ldmatrix to registers ----
#pragma unroll
    for (int p = 0; p < 4; ++p) {
        int row = r32 + p * 32;
        bf16* dst = (row < 64) ? &Ks[row * KSTRIDE + cg8] : &Vs[(row - 64) * KSTRIDE + cg8];
        *(uint4*)dst = *(const uint4*)(q + ((size_t)(b * S + q0 + row)) * E + h * HD + cg8);
    }
    __syncthreads();

    uint32_t a_q[4][4];
    {
        int lrow = lane & 15, lcol = (lane >> 4) * 8;
        const bf16* base = (w < 4) ? &Ks[(w * 16 + lrow) * KSTRIDE]
                                   : &Vs[((w - 4) * 16 + lrow) * KSTRIDE];
#pragma unroll
        for (int kc = 0; kc < 4; ++kc)
            ldsm_x4(a_q[kc], sptr(base + kc * 16 + lcol));
    }

    float mr0 = -1e30f, mr1 = -1e30f, l0 = 0.0f, l1 = 0.0f;
    float o[8][4] = {};

    const int kb_row = (lane & 7) + ((lane & 16) ? 8 : 0);
    const int kb_col = (lane & 8) ? 8 : 0;
    const int vb_row = (lane & 7) + ((lane & 8) ? 8 : 0);
    const int vb_col = (lane & 16) ? 8 : 0;

    const size_t kvg0 = ((size_t)(b * S) + r32) * E + h * HD + cg8;
    uint4 kr0, kr1, vr0, vr1;
    {
        size_t g = kvg0;
        kr0 = *(const uint4*)(k + g); kr1 = *(const uint4*)(k + g + (size_t)32 * E);
        vr0 = *(const uint4*)(v + g); vr1 = *(const uint4*)(v + g + (size_t)32 * E);
    }
    __syncthreads();   // Q reads complete before first KV store

    for (int kt = 0; kt < S / 64; ++kt) {
        *(uint4*)&Ks[r32 * KSTRIDE + cg8]        = kr0;
        *(uint4*)&Ks[(r32 + 32) * KSTRIDE + cg8] = kr1;
        *(uint4*)&Vs[r32 * KSTRIDE + cg8]        = vr0;
        *(uint4*)&Vs[(r32 + 32) * KSTRIDE + cg8] = vr1;
        __syncthreads();
        if (kt + 1 < S / 64) {
            size_t g = kvg0 + (size_t)(kt + 1) * 64 * E;
            kr0 = *(const uint4*)(k + g); kr1 = *(const uint4*)(k + g + (size_t)32 * E);
            vr0 = *(const uint4*)(v + g); vr1 = *(const uint4*)(v + g + (size_t)32 * E);
        }

        // ---- S = Q K^T ----
        float s[8][4] = {};
#pragma unroll
        for (int kc = 0; kc < 4; ++kc) {
#pragma unroll
            for (int nb2 = 0; nb2 < 4; ++nb2) {
                uint32_t bb[4];
                ldsm_x4(bb, sptr(&Ks[(nb2 * 16 + kb_row) * KSTRIDE + kc * 16 + kb_col]));
                mma_bf16(s[nb2 * 2],     a_q[kc], bb[0], bb[1]);
                mma_bf16(s[nb2 * 2 + 1], a_q[kc], bb[2], bb[3]);
            }
        }

        // ---- online softmax ----
        float mx0 = -1e30f, mx1 = -1e30f;
#pragma unroll
        for (int j = 0; j < 8; ++j) {
            mx0 = fmaxf(mx0, fmaxf(s[j][0], s[j][1]));
            mx1 = fmaxf(mx1, fmaxf(s[j][2], s[j][3]));
        }
        mx0 = fmaxf(mx0, __shfl_xor_sync(0xffffffffu, mx0, 1));
        mx0 = fmaxf(mx0, __shfl_xor_sync(0xffffffffu, mx0, 2));
        mx1 = fmaxf(mx1, __shfl_xor_sync(0xffffffffu, mx1, 1));
        mx1 = fmaxf(mx1, __shfl_xor_sync(0xffffffffu, mx1, 2));
        float mn0 = fmaxf(mr0, mx0), mn1 = fmaxf(mr1, mx1);
        float c0 = __expf(mr0 - mn0), c1 = __expf(mr1 - mn1);

        uint32_t pA[8], pB[8];
        float sum0 = 0.0f, sum1 = 0.0f;
#pragma unroll
        for (int j = 0; j < 8; ++j) {
            float p00 = __expf(s[j][0] - mn0);
            float p01 = __expf(s[j][1] - mn0);
            float p10 = __expf(s[j][2] - mn1);
            float p11 = __expf(s[j][3] - mn1);
            sum0 += p00 + p01;
            sum1 += p10 + p11;
            pA[j] = pack_bf16(p00, p01);
            pB[j] = pack_bf16(p10, p11);
        }
        sum0 += __shfl_xor_sync(0xffffffffu, sum0, 1);
        sum0 += __shfl_xor_sync(0xffffffffu, sum0, 2);
        sum1 += __shfl_xor_sync(0xffffffffu, sum1, 1);
        sum1 += __shfl_xor_sync(0xffffffffu, sum1, 2);
        l0 = l0 * c0 + sum0;
        l1 = l1 * c1 + sum1;
#pragma unroll
        for (int j = 0; j < 8; ++j) {
            o[j][0] *= c0; o[j][1] *= c0;
            o[j][2] *= c1; o[j][3] *= c1;
        }
        mr0 = mn0; mr1 = mn1;

        // ---- O += P V ----
#pragma unroll
        for (int kc = 0; kc < 4; ++kc) {
            uint32_t ap[4] = {pA[2 * kc], pB[2 * kc], pA[2 * kc + 1], pB[2 * kc + 1]};
#pragma unroll
            for (int nb2 = 0; nb2 < 4; ++nb2) {
                uint32_t bb[4];
                ldsm_x4_t(bb, sptr(&Vs[(kc * 16 + vb_row) * KSTRIDE + nb2 * 16 + vb_col]));
                mma_bf16(o[nb2 * 2],     ap, bb[0], bb[1]);
                mma_bf16(o[nb2 * 2 + 1], ap, bb[2], bb[3]);
            }
        }
        __syncthreads();
    }

    // ---- epilogue (bf16 out) ----
    float i0 = 1.0f / l0, i1 = 1.0f / l1;
    int row0 = q0 + w * 16 + (lane >> 2);
    int colb = h * HD + (lane & 3) * 2;
    bf16* out0 = out + ((size_t)(b * S + row0)) * E + colb;
    bf16* out1 = out0 + 8 * (size_t)E;
#pragma unroll
    for (int j = 0; j < 8; ++j) {
        *(uint32_t*)(out0 + j * 8) = pack_bf16(o[j][0] * i0, o[j][1] * i0);
        *(uint32_t*)(out1 + j * 8) = pack_bf16(o[j][2] * i1, o[j][3] * i1);
    }
}

// ---------------- launcher ---------------------------------------------------
extern "C" void kernel_launch(void* const* d_in, const int* in_sizes, int n_in,
                              void* d_out, int out_size) {
    const float* x    = (const float*)d_in[0];
    const float* cond = (const float*)d_in[1];
    const float* ln1w = (const float*)d_in[14];
    const float* ln1b = (const float*)d_in[15];
    const float* ln2w = (const float*)d_in[16];
    const float* ln2b = (const float*)d_in[17];
    const float* wq   = (const float*)d_in[18];
    const float* wk   = (const float*)d_in[19];
    const float* wv   = (const float*)d_in[20];
    const float* wo   = (const float*)d_in[21];
    const float* ff1w = (const float*)d_in[22];
    const float* ff1b = (const float*)d_in[23];
    const float* ff2w = (const float*)d_in[24];
    const float* ff2b = (const float*)d_in[25];

    float *mod, *y;
    bf16 *ymod, *zmod, *qb, *kb, *vb, *att, *hb;
    bf16 *wqb, *wkb, *wvb, *wob, *ff1b_, *ff2b_;
    cudaGetSymbolAddress((void**)&mod,   g_mod);
    cudaGetSymbolAddress((void**)&ymod,  g_ymod);
    cudaGetSymbolAddress((void**)&zmod,  g_zmod);
    cudaGetSymbolAddress((void**)&qb,    g_q);
    cudaGetSymbolAddress((void**)&kb,    g_k);
    cudaGetSymbolAddress((void**)&vb,    g_v);
    cudaGetSymbolAddress((void**)&att,   g_att);
    cudaGetSymbolAddress((void**)&hb,    g_h);
    cudaGetSymbolAddress((void**)&y,     g_y);
    cudaGetSymbolAddress((void**)&wqb,   g_wq);
    cudaGetSymbolAddress((void**)&wkb,   g_wk);
    cudaGetSymbolAddress((void**)&wvb,   g_wv);
    cudaGetSymbolAddress((void**)&wob,   g_wo);
    cudaGetSymbolAddress((void**)&ff1b_, g_ff1);
    cudaGetSymbolAddress((void**)&ff2b_, g_ff2);

    CondW P;
    P.w[0] = (const float*)d_in[2];  P.b[0] = (const float*)d_in[3];
    P.w[1] = (const float*)d_in[4];  P.b[1] = (const float*)d_in[5];
    P.w[2] = (const float*)d_in[6];  P.b[2] = (const float*)d_in[7];
    P.w[3] = (const float*)d_in[8];  P.b[3] = (const float*)d_in[9];
    P.w[4] = (const float*)d_in[10]; P.b[4] = (const float*)d_in[11];
    P.w[5] = (const float*)d_in[12]; P.b[5] = (const float*)d_in[13];

    const float* gamma1 = mod + 0 * BATCH * E;
    const float* beta1  = mod + 1 * BATCH * E;
    const float* alpha1 = mod + 2 * BATCH * E;
    const float* gamma2 = mod + 3 * BATCH * E;
    const float* beta2  = mod + 4 * BATCH * E;
    const float* alpha2 = mod + 5 * BATCH * E;

    // weight conversions (fp32 -> bf16)
    int nEE = E * E / 4, nEH = E * HID / 4;
    f2b_k<<<(nEE + 255) / 256, 256>>>(wq,   wqb,   nEE);
    f2b_k<<<(nEE + 255) / 256, 256>>>(wk,   wkb,   nEE);
    f2b_k<<<(nEE + 255) / 256, 256>>>(wv,   wvb,   nEE);
    f2b_k<<<(nEE + 255) / 256, 256>>>(wo,   wob,   nEE);
    f2b_k<<<(nEH + 255) / 256, 256>>>(ff1w, ff1b_, nEH);
    f2b_k<<<(nEH + 255) / 256, 256>>>(ff2w, ff2b_, nEH);

    cond_proj_k<<<24, E>>>(cond, P, mod);
    ln_mod_k<<<NROWS, 128>>>(x, ln1w, ln1b, gamma1, beta1, ymod);

    // fused QKV (gridDim.z = 3)
    dim3 gQKV(E / 128, NROWS / 128, 3);
    gemm_bf16_k<0><<<gQKV, 256>>>(ymod, wqb, nullptr, nullptr, nullptr, qb,
                                  NROWS, E, E, 0.125f, wkb, wvb, kb, vb);

    attn_mma_k<<<dim3(S / 128, BATCH * NH), 256>>>(qb, kb, vb, att);

    dim3 gE(E / 128, NROWS / 128);
    gemm_bf16_k<1><<<gE, 256>>>(att, wob, nullptr, alpha1, x, y,
                                NROWS, E, E, 1.0f, nullptr, nullptr, nullptr, nullptr);

    ln_mod_k<<<NROWS, 128>>>(y, ln2w, ln2b, gamma2, beta2, zmod);

    dim3 gH(HID / 128, NROWS / 128);
    gemm_bf16_k<2><<<gH, 256>>>(zmod, ff1b_, ff1b, nullptr, nullptr, hb,
                                NROWS, HID, E, 1.0f, nullptr, nullptr, nullptr, nullptr);
    gemm_bf16_k<3><<<gE, 256>>>(hb, ff2b_, ff2b, alpha2, y, d_out,
                                NROWS, E, HID, 1.0f, nullptr, nullptr, nullptr, nullptr);
}

// round 4
// speedup vs baseline: 14.6265x; 1.1328x over previous
#include <cuda_runtime.h>
#include <cuda_bf16.h>
#include <cstdint>
#include <cstddef>

#define E 384
#define S 4096
#define BATCH 4
#define NROWS (BATCH * S)      // 16384
#define HID 1536
#define NH 6
#define HD 64

typedef __nv_bfloat16 bf16;

// ---------------- scratch (device globals — no runtime allocation) ----------
__device__ float g_mod[6 * BATCH * E];
__device__ bf16  g_ymod[(size_t)NROWS * E];
__device__ bf16  g_zmod[(size_t)NROWS * E];
__device__ bf16  g_q[(size_t)NROWS * E];
__device__ bf16  g_k[(size_t)NROWS * E];
__device__ bf16  g_v[(size_t)NROWS * E];
__device__ bf16  g_att[(size_t)NROWS * E];
__device__ bf16  g_h[(size_t)NROWS * HID];
__device__ float g_y[(size_t)NROWS * E];
__device__ bf16 g_wq[E * E];
__device__ bf16 g_wk[E * E];
__device__ bf16 g_wv[E * E];
__device__ bf16 g_wo[E * E];
__device__ bf16 g_ff1[E * HID];
__device__ bf16 g_ff2[HID * E];

// ---------------- small helpers --------------------------------------------
__device__ __forceinline__ uint32_t sptr(const void* p) {
    return (uint32_t)__cvta_generic_to_shared(p);
}
__device__ __forceinline__ void ldsm_x4(uint32_t* r, uint32_t addr) {
    asm volatile("ldmatrix.sync.aligned.m8n8.x4.shared.b16 {%0,%1,%2,%3}, [%4];"
                 : "=r"(r[0]), "=r"(r[1]), "=r"(r[2]), "=r"(r[3]) : "r"(addr));
}
__device__ __forceinline__ void ldsm_x4_t(uint32_t* r, uint32_t addr) {
    asm volatile("ldmatrix.sync.aligned.m8n8.x4.trans.shared.b16 {%0,%1,%2,%3}, [%4];"
                 : "=r"(r[0]), "=r"(r[1]), "=r"(r[2]), "=r"(r[3]) : "r"(addr));
}
__device__ __forceinline__ void mma_bf16(float* c, const uint32_t* a,
                                         uint32_t b0, uint32_t b1) {
    asm volatile(
        "mma.sync.aligned.m16n8k16.row.col.f32.bf16.bf16.f32 "
        "{%0,%1,%2,%3}, {%4,%5,%6,%7}, {%8,%9}, {%0,%1,%2,%3};"
        : "+f"(c[0]), "+f"(c[1]), "+f"(c[2]), "+f"(c[3])
        : "r"(a[0]), "r"(a[1]), "r"(a[2]), "r"(a[3]), "r"(b0), "r"(b1));
}
__device__ __forceinline__ uint32_t pack_bf16(float lo, float hi) {
    __nv_bfloat162 h2 = __floats2bfloat162_rn(lo, hi);
    return *reinterpret_cast<uint32_t*>(&h2);
}
__device__ __forceinline__ float ex2(float x) {
    float y;
    asm("ex2.approx.ftz.f32 %0, %1;" : "=f"(y) : "f"(x));
    return y;
}
__device__ __forceinline__ void cp_async16(uint32_t saddr, const void* gptr) {
    asm volatile("cp.async.cg.shared.global [%0], [%1], 16;" :: "r"(saddr), "l"(gptr));
}
__device__ __forceinline__ void cp_commit() {
    asm volatile("cp.async.commit_group;");
}
template <int N> __device__ __forceinline__ void cp_wait() {
    asm volatile("cp.async.wait_group %0;" :: "n"(N));
}

// ---------------- fused fp32 -> bf16 weight conversion ----------------------
struct F2B { const float* s[6]; bf16* d[6]; };

__global__ void f2b_all_k(F2B t) {
    int bid = blockIdx.x;
    int seg, base;
    if (bid < 576) { seg = bid / 144; base = bid % 144; }          // 4x E*E (36864 f4)
    else { seg = 4 + (bid - 576) / 576; base = (bid - 576) % 576; } // 2x E*HID (147456 f4)
    int i = base * 256 + threadIdx.x;
    float4 v = ((const float4*)t.s[seg])[i];
    uint32_t pk[2] = {pack_bf16(v.x, v.y), pack_bf16(v.z, v.w)};
    ((uint2*)t.d[seg])[i] = *(uint2*)pk;
}

// ---------------- cond projections ------------------------------------------
struct CondW { const float* w[6]; const float* b[6]; };

__global__ void cond_proj_k(const float* __restrict__ cond, CondW P,
                            float* __restrict__ mod) {
    int proj = blockIdx.x >> 2;
    int bb   = blockIdx.x & 3;
    __shared__ float cs[E];
    int t = threadIdx.x;
    cs[t] = cond[bb * E + t];
    __syncthreads();
    const float* W = P.w[proj];
    float acc = P.b[proj][t];
#pragma unroll 4
    for (int kk = 0; kk < E; ++kk) acc = fmaf(cs[kk], W[kk * E + t], acc);
    mod[(proj * BATCH + bb) * E + t] = acc;
}

// ---------------- LayerNorm + AdaLN modulate (bf16 out) ---------------------
__global__ void __launch_bounds__(128)
ln_mod_k(const float* __restrict__ in,
         const float* __restrict__ lnw, const float* __restrict__ lnb,
         const float* __restrict__ gamma, const float* __restrict__ beta,
         bf16* __restrict__ out) {
    int row = blockIdx.x, t = threadIdx.x;
    int bb = row >> 12;
    const float* xr = in + (size_t)row * E;
    float v0 = xr[t], v1 = xr[t + 128], v2 = xr[t + 256];
    float s  = v0 + v1 + v2;
    float sq = v0 * v0 + v1 * v1 + v2 * v2;
#pragma unroll
    for (int off = 16; off; off >>= 1) {
        s  += __shfl_xor_sync(0xffffffffu, s,  off);
        sq += __shfl_xor_sync(0xffffffffu, sq, off);
    }
    __shared__ float rs[4], rq[4];
    int w = t >> 5;
    if ((t & 31) == 0) { rs[w] = s; rq[w] = sq; }
    __syncthreads();
    s  = rs[0] + rs[1] + rs[2] + rs[3];
    sq = rq[0] + rq[1] + rq[2] + rq[3];
    float mean = s * (1.0f / E);
    float var  = sq * (1.0f / E) - mean * mean;
    float rstd = rsqrtf(var + 1e-5f);
    bf16* orow = out + (size_t)row * E;
    const float* g  = gamma + bb * E;
    const float* be = beta  + bb * E;
    float vv[3] = {v0, v1, v2};
#pragma unroll
    for (int i = 0; i < 3; ++i) {
        int e = t + i * 128;
        float val = (vv[i] - mean) * rstd * lnw[e] + lnb[e];
        orow[e] = __float2bfloat16(fmaf(val, g[e], val + be[e]));
    }
}

// ---------------- bf16 tensor-core GEMM, cp.async double-buffered -----------
// EPI 0: bf16 out, *scale (qkv; gridDim.z selects wq/wk/wv)
// EPI 1: f32 out, res + C*alpha            (wo)
// EPI 2: bf16 out, relu(C + bias)          (ff1)
// EPI 3: f32 out, res + (C+bias)*alpha     (ff2 -> final)
#define ASTR 40
#define BSTR 136

template <int EPI>
__global__ void __launch_bounds__(256, 2)
gemm_bf16_k(const bf16* __restrict__ A, const bf16* __restrict__ W,
            const float* __restrict__ bias, const float* __restrict__ alpha,
            const float* __restrict__ res, void* __restrict__ Cv,
            int M, int N, int K, float scale,
            const bf16* W2, const bf16* W3, void* C2, void* C3) {
    __shared__ bf16 As[2][128 * ASTR];
    __shared__ bf16 Bs[2][32 * BSTR];

    if (EPI == 0) {
        int z = blockIdx.z;
        if (z == 1) { W = W2; Cv = C2; scale = 1.0f; }
        else if (z == 2) { W = W3; Cv = C3; scale = 1.0f; }
    }

    const int tid = threadIdx.x;
    const int lane = tid & 31, wid = tid >> 5;
    const int bm = blockIdx.y * 128;
    const int bn = blockIdx.x * 128;
    const int warp_m = wid >> 2, warp_n = wid & 3;

    // cp.async chunk mappings (each thread: 2 A-chunks + 2 B-chunks of 16B)
    const int a_row = tid >> 2, a_col = (tid & 3) * 8;
    const int b_row = tid >> 4, b_col = (tid & 15) * 8;
    const bf16* Abase = A + (size_t)(bm + a_row) * K + a_col;
    const bf16* Wbase = W + (size_t)b_row * N + bn + b_col;

    const int nk = K / 32;
    auto load_tile = [&](int st, int kb) {
        const bf16* Ab = Abase + kb * 32;
        cp_async16(sptr(&As[st][a_row * ASTR + a_col]), Ab);
        cp_async16(sptr(&As[st][(a_row + 64) * ASTR + a_col]), Ab + (size_t)64 * K);
        const bf16* Bb = Wbase + (size_t)(kb * 32) * N;
        cp_async16(sptr(&Bs[st][b_row * BSTR + b_col]), Bb);
        cp_async16(sptr(&Bs[st][(b_row + 16) * BSTR + b_col]), Bb + (size_t)16 * N);
        cp_commit();
    };

    load_tile(0, 0);
    if (nk > 1) load_tile(1, 1);

    float acc[4][4][4] = {};
    const int lrow = lane & 15, lcol = (lane >> 4) * 8;
    const int tb_row = (lane & 7) + ((lane & 8) ? 8 : 0);
    const int tb_col = (lane & 16) ? 8 : 0;

    for (int kb = 0; kb < nk; ++kb) {
        if (kb + 1 < nk) cp_wait<1>(); else cp_wait<0>();
        __syncthreads();
        const int st = kb & 1;
#pragma unroll
        for (int ks = 0; ks < 2; ++ks) {
            uint32_t af[4][4];
#pragma unroll
            for (int mi = 0; mi < 4; ++mi)
                ldsm_x4(af[mi], sptr(&As[st][(warp_m * 64 + mi * 16 + lrow) * ASTR + ks * 16 + lcol]));
            uint32_t bf_[2][4];
#pragma unroll
            for (int ni2 = 0; ni2 < 2; ++ni2)
                ldsm_x4_t(bf_[ni2], sptr(&Bs[st][(ks * 16 + tb_row) * BSTR + warp_n * 32 + ni2 * 16 + tb_col]));
#pragma unroll
            for (int mi = 0; mi < 4; ++mi) {
#pragma unroll
                for (int ni2 = 0; ni2 < 2; ++ni2) {
                    mma_bf16(acc[mi][ni2 * 2],     af[mi], bf_[ni2][0], bf_[ni2][1]);
                    mma_bf16(acc[mi][ni2 * 2 + 1], af[mi], bf_[ni2][2], bf_[ni2][3]);
                }
            }
        }
        __syncthreads();
        if (kb + 2 < nk) load_tile(st, kb + 2);
    }

    // epilogue
#pragma unroll
    for (int mi = 0; mi < 4; ++mi) {
#pragma unroll
        for (int rr = 0; rr < 2; ++rr) {
            int row = bm + warp_m * 64 + mi * 16 + (lane >> 2) + rr * 8;
            int bIdx = row >> 12;
            size_t rowoff = (size_t)row * N;
#pragma unroll
            for (int ni = 0; ni < 4; ++ni) {
                int col = bn + warp_n * 32 + ni * 8 + (lane & 3) * 2;
                float c0 = acc[mi][ni][rr * 2], c1 = acc[mi][ni][rr * 2 + 1];
                if (EPI == 0) {
                    *(uint32_t*)((bf16*)Cv + rowoff + col) = pack_bf16(c0 * scale, c1 * scale);
                } else if (EPI == 2) {
                    float t0 = fmaxf(c0 + bias[col], 0.0f);
                    float t1 = fmaxf(c1 + bias[col + 1], 0.0f);
                    *(uint32_t*)((bf16*)Cv + rowoff + col) = pack_bf16(t0, t1);
                } else if (EPI == 1) {
                    float2 r = *(const float2*)(res + rowoff + col);
                    float a0f = alpha[bIdx * E + col], a1f = alpha[bIdx * E + col + 1];
                    *(float2*)((float*)Cv + rowoff + col) =
                        make_float2(r.x + c0 * a0f, r.y + c1 * a1f);
                } else {  // EPI == 3
                    float2 r = *(const float2*)(res + rowoff + col);
                    float a0f = alpha[bIdx * E + col], a1f = alpha[bIdx * E + col + 1];
                    *(float2*)((float*)Cv + rowoff + col) =
                        make_float2(r.x + (c0 + bias[col]) * a0f,
                                    r.y + (c1 + bias[col + 1]) * a1f);
                }
            }
        }
    }
}

// ---------------- flash attention v2, bf16 mma, cp.async pipelined ----------
// block = 256 threads (8 warps), Q tile 128 rows, KV tiles 64 keys, 2 stages.
// Scores arrive in log2 domain (q pre-scaled by 0.125*log2e) -> ex2 softmax.
#define KSTRIDE 72

__global__ void __launch_bounds__(256, 2)
attn_mma_k(const bf16* __restrict__ q, const bf16* __restrict__ k,
           const bf16* __restrict__ v, bf16* __restrict__ out) {
    __shared__ bf16 Ks[2][64 * KSTRIDE];
    __shared__ bf16 Vs[2][64 * KSTRIDE];

    const int tid = threadIdx.x;
    const int lane = tid & 31, w = tid >> 5;
    const int bh = blockIdx.y;
    const int b = bh / NH, h = bh % NH;
    const int q0 = blockIdx.x * 128;

    const int kv_row = tid >> 3;            // 0..31
    const int kv_col = (tid & 7) * 8;

    // ---- stage Q tile (128 rows) through Ks[0]/Ks[1], ldmatrix to regs ----
#pragma unroll
    for (int p = 0; p < 4; ++p) {
        int row = kv_row + p * 32;
        bf16* dst = (row < 64) ? &Ks[0][row * KSTRIDE + kv_col]
                               : &Ks[1][(row - 64) * KSTRIDE + kv_col];
        *(uint4*)dst = *(const uint4*)(q + ((size_t)(b * S + q0 + row)) * E + h * HD + kv_col);
    }
    __syncthreads();

    uint32_t a_q[4][4];
    {
        int lrow = lane & 15, lcol = (lane >> 4) * 8;
        const bf16* base = (w < 4) ? &Ks[0][(w * 16 + lrow) * KSTRIDE]
                                   : &Ks[1][((w - 4) * 16 + lrow) * KSTRIDE];
#pragma unroll
        for (int kc = 0; kc < 4; ++kc)
            ldsm_x4(a_q[kc], sptr(base + kc * 16 + lcol));
    }
    __syncthreads();    // Q reads complete before cp.async overwrites Ks

    const bf16* kbase = k + ((size_t)(b * S) + kv_row) * E + h * HD + kv_col;
    const bf16* vbase = v + ((size_t)(b * S) + kv_row) * E + h * HD + kv_col;
    auto load_kv = [&](int st, int kt) {
        const bf16* kp = kbase + (size_t)(kt * 64) * E;
        const bf16* vp = vbase + (size_t)(kt * 64) * E;
        cp_async16(sptr(&Ks[st][kv_row * KSTRIDE + kv_col]), kp);
        cp_async16(sptr(&Ks[st][(kv_row + 32) * KSTRIDE + kv_col]), kp + (size_t)32 * E);
        cp_async16(sptr(&Vs[st][kv_row * KSTRIDE + kv_col]), vp);
        cp_async16(sptr(&Vs[st][(kv_row + 32) * KSTRIDE + kv_col]), vp + (size_t)32 * E);
        cp_commit();
    };
    load_kv(0, 0);
    load_kv(1, 1);

    float mr0 = -1e30f, mr1 = -1e30f, l0 = 0.0f, l1 = 0.0f;
    float o[8][4] = {};

    const int kb_row = (lane & 7) + ((lane & 16) ? 8 : 0);
    const int kb_col = (lane & 8) ? 8 : 0;
    const int vb_row = (lane & 7) + ((lane & 8) ? 8 : 0);
    const int vb_col = (lane & 16) ? 8 : 0;

    const int nt = S / 64;
    for (int kt = 0; kt < nt; ++kt) {
        if (kt + 1 < nt) cp_wait<1>(); else cp_wait<0>();
        __syncthreads();
        const int st = kt & 1;

        // ---- S = Q K^T (log2 domain) ----
        float s[8][4] = {};
#pragma unroll
        for (int kc = 0; kc < 4; ++kc) {
#pragma unroll
            for (int nb2 = 0; nb2 < 4; ++nb2) {
                uint32_t bb[4];
                ldsm_x4(bb, sptr(&Ks[st][(nb2 * 16 + kb_row) * KSTRIDE + kc * 16 + kb_col]));
                mma_bf16(s[nb2 * 2],     a_q[kc], bb[0], bb[1]);
                mma_bf16(s[nb2 * 2 + 1], a_q[kc], bb[2], bb[3]);
            }
        }

        // ---- online softmax (base-2) ----
        float mx0 = -1e30f, mx1 = -1e30f;
#pragma unroll
        for (int j = 0; j < 8; ++j) {
            mx0 = fmaxf(mx0, fmaxf(s[j][0], s[j][1]));
            mx1 = fmaxf(mx1, fmaxf(s[j][2], s[j][3]));
        }
        mx0 = fmaxf(mx0, __shfl_xor_sync(0xffffffffu, mx0, 1));
        mx0 = fmaxf(mx0, __shfl_xor_sync(0xffffffffu, mx0, 2));
        mx1 = fmaxf(mx1, __shfl_xor_sync(0xffffffffu, mx1, 1));
        mx1 = fmaxf(mx1, __shfl_xor_sync(0xffffffffu, mx1, 2));
        float mn0 = fmaxf(mr0, mx0), mn1 = fmaxf(mr1, mx1);
        float c0 = ex2(mr0 - mn0), c1 = ex2(mr1 - mn1);

        uint32_t pA[8], pB[8];
        float sum0 = 0.0f, sum1 = 0.0f;
#pragma unroll
        for (int j = 0; j < 8; ++j) {
            float p00 = ex2(s[j][0] - mn0);
            float p01 = ex2(s[j][1] - mn0);
            float p10 = ex2(s[j][2] - mn1);
            float p11 = ex2(s[j][3] - mn1);
            sum0 += p00 + p01;
            sum1 += p10 + p11;
            pA[j] = pack_bf16(p00, p01);
            pB[j] = pack_bf16(p10, p11);
        }
        sum0 += __shfl_xor_sync(0xffffffffu, sum0, 1);
        sum0 += __shfl_xor_sync(0xffffffffu, sum0, 2);
        sum1 += __shfl_xor_sync(0xffffffffu, sum1, 1);
        sum1 += __shfl_xor_sync(0xffffffffu, sum1, 2);
        l0 = l0 * c0 + sum0;
        l1 = l1 * c1 + sum1;
#pragma unroll
        for (int j = 0; j < 8; ++j) {
            o[j][0] *= c0; o[j][1] *= c0;
            o[j][2] *= c1; o[j][3] *= c1;
        }
        mr0 = mn0; mr1 = mn1;

        // ---- O += P V ----
#pragma unroll
        for (int kc = 0; kc < 4; ++kc) {
            uint32_t ap[4] = {pA[2 * kc], pB[2 * kc], pA[2 * kc + 1], pB[2 * kc + 1]};
#pragma unroll
            for (int nb2 = 0; nb2 < 4; ++nb2) {
                uint32_t bb[4];
                ldsm_x4_t(bb, sptr(&Vs[st][(kc * 16 + vb_row) * KSTRIDE + nb2 * 16 + vb_col]));
                mma_bf16(o[nb2 * 2],     ap, bb[0], bb[1]);
                mma_bf16(o[nb2 * 2 + 1], ap, bb[2], bb[3]);
            }
        }
        __syncthreads();
        if (kt + 2 < nt) load_kv(st, kt + 2);
    }

    // ---- epilogue (bf16 out) ----
    float i0 = 1.0f / l0, i1 = 1.0f / l1;
    int row0 = q0 + w * 16 + (lane >> 2);
    int colb = h * HD + (lane & 3) * 2;
    bf16* out0 = out + ((size_t)(b * S + row0)) * E + colb;
    bf16* out1 = out0 + 8 * (size_t)E;
#pragma unroll
    for (int j = 0; j < 8; ++j) {
        *(uint32_t*)(out0 + j * 8) = pack_bf16(o[j][0] * i0, o[j][1] * i0);
        *(uint32_t*)(out1 + j * 8) = pack_bf16(o[j][2] * i1, o[j][3] * i1);
    }
}

// ---------------- launcher ---------------------------------------------------
extern "C" void kernel_launch(void* const* d_in, const int* in_sizes, int n_in,
                              void* d_out, int out_size) {
    const float* x    = (const float*)d_in[0];
    const float* cond = (const float*)d_in[1];
    const float* ln1w = (const float*)d_in[14];
    const float* ln1b = (const float*)d_in[15];
    const float* ln2w = (const float*)d_in[16];
    const float* ln2b = (const float*)d_in[17];
    const float* ff1b = (const float*)d_in[23];
    const float* ff2b = (const float*)d_in[25];

    float *mod, *y;
    bf16 *ymod, *zmod, *qb, *kb, *vb, *att, *hb;
    bf16 *wqb, *wkb, *wvb, *wob, *ff1w_, *ff2w_;
    cudaGetSymbolAddress((void**)&mod,   g_mod);
    cudaGetSymbolAddress((void**)&ymod,  g_ymod);
    cudaGetSymbolAddress((void**)&zmod,  g_zmod);
    cudaGetSymbolAddress((void**)&qb,    g_q);
    cudaGetSymbolAddress((void**)&kb,    g_k);
    cudaGetSymbolAddress((void**)&vb,    g_v);
    cudaGetSymbolAddress((void**)&att,   g_att);
    cudaGetSymbolAddress((void**)&hb,    g_h);
    cudaGetSymbolAddress((void**)&y,     g_y);
    cudaGetSymbolAddress((void**)&wqb,   g_wq);
    cudaGetSymbolAddress((void**)&wkb,   g_wk);
    cudaGetSymbolAddress((void**)&wvb,   g_wv);
    cudaGetSymbolAddress((void**)&wob,   g_wo);
    cudaGetSymbolAddress((void**)&ff1w_, g_ff1);
    cudaGetSymbolAddress((void**)&ff2w_, g_ff2);

    CondW P;
    P.w[0] = (const float*)d_in[2];  P.b[0] = (const float*)d_in[3];
    P.w[1] = (const float*)d_in[4];  P.b[1] = (const float*)d_in[5];
    P.w[2] = (const float*)d_in[6];  P.b[2] = (const float*)d_in[7];
    P.w[3] = (const float*)d_in[8];  P.b[3] = (const float*)d_in[9];
    P.w[4] = (const float*)d_in[10]; P.b[4] = (const float*)d_in[11];
    P.w[5] = (const float*)d_in[12]; P.b[5] = (const float*)d_in[13];

    const float* gamma1 = mod + 0 * BATCH * E;
    const float* beta1  = mod + 1 * BATCH * E;
    const float* alpha1 = mod + 2 * BATCH * E;
    const float* gamma2 = mod + 3 * BATCH * E;
    const float* beta2  = mod + 4 * BATCH * E;
    const float* alpha2 = mod + 5 * BATCH * E;

    // fused weight conversions (fp32 -> bf16), one launch
    F2B T;
    T.s[0] = (const float*)d_in[18]; T.d[0] = wqb;
    T.s[1] = (const float*)d_in[19]; T.d[1] = wkb;
    T.s[2] = (const float*)d_in[20]; T.d[2] = wvb;
    T.s[3] = (const float*)d_in[21]; T.d[3] = wob;
    T.s[4] = (const float*)d_in[22]; T.d[4] = ff1w_;
    T.s[5] = (const float*)d_in[24]; T.d[5] = ff2w_;
    f2b_all_k<<<1728, 256>>>(T);

    cond_proj_k<<<24, E>>>(cond, P, mod);
    ln_mod_k<<<NROWS, 128>>>(x, ln1w, ln1b, gamma1, beta1, ymod);

    // fused QKV (gridDim.z = 3); q scaled by 0.125 * log2(e) for ex2 softmax
    dim3 gQKV(E / 128, NROWS / 128, 3);
    gemm_bf16_k<0><<<gQKV, 256>>>(ymod, wqb, nullptr, nullptr, nullptr, qb,
                                  NROWS, E, E, 0.18033688f, wkb, wvb, kb, vb);

    attn_mma_k<<<dim3(S / 128, BATCH * NH), 256>>>(qb, kb, vb, att);

    dim3 gE(E / 128, NROWS / 128);
    gemm_bf16_k<1><<<gE, 256>>>(att, wob, nullptr, alpha1, x, y,
                                NROWS, E, E, 1.0f, nullptr, nullptr, nullptr, nullptr);

    ln_mod_k<<<NROWS, 128>>>(y, ln2w, ln2b, gamma2, beta2, zmod);

    dim3 gH(HID / 128, NROWS / 128);
    gemm_bf16_k<2><<<gH, 256>>>(zmod, ff1w_, ff1b, nullptr, nullptr, hb,
                                NROWS, HID, E, 1.0f, nullptr, nullptr, nullptr, nullptr);
    gemm_bf16_k<3><<<gE, 256>>>(hb, ff2w_, ff2b, alpha2, y, d_out,
                                NROWS, E, HID, 1.0f, nullptr, nullptr, nullptr, nullptr);
}

// round 5
// speedup vs baseline: 15.1243x; 1.0340x over previous
#include <cuda_runtime.h>
#include <cuda_bf16.h>
#include <cuda_fp16.h>
#include <cstdint>
#include <cstddef>

#define E 384
#define S 4096
#define BATCH 4
#define NROWS (BATCH * S)      // 16384
#define HID 1536
#define NH 6
#define HD 64

typedef __nv_bfloat16 bf16;

// ---------------- scratch (device globals — no runtime allocation) ----------
__device__ float  g_mod[6 * BATCH * E];
__device__ bf16   g_ymod[(size_t)NROWS * E];
__device__ bf16   g_zmod[(size_t)NROWS * E];
__device__ bf16   g_q[(size_t)NROWS * E];
__device__ bf16   g_k[(size_t)NROWS * E];
__device__ __half g_v[(size_t)NROWS * E];
__device__ bf16   g_att[(size_t)NROWS * E];
__device__ bf16   g_h[(size_t)NROWS * HID];
__device__ float  g_y[(size_t)NROWS * E];
__device__ bf16 g_wq[E * E];
__device__ bf16 g_wk[E * E];
__device__ bf16 g_wv[E * E];
__device__ bf16 g_wo[E * E];
__device__ bf16 g_ff1[E * HID];
__device__ bf16 g_ff2[HID * E];

// ---------------- small helpers --------------------------------------------
__device__ __forceinline__ uint32_t sptr(const void* p) {
    return (uint32_t)__cvta_generic_to_shared(p);
}
__device__ __forceinline__ void ldsm_x4(uint32_t* r, uint32_t addr) {
    asm volatile("ldmatrix.sync.aligned.m8n8.x4.shared.b16 {%0,%1,%2,%3}, [%4];"
                 : "=r"(r[0]), "=r"(r[1]), "=r"(r[2]), "=r"(r[3]) : "r"(addr));
}
__device__ __forceinline__ void ldsm_x4_t(uint32_t* r, uint32_t addr) {
    asm volatile("ldmatrix.sync.aligned.m8n8.x4.trans.shared.b16 {%0,%1,%2,%3}, [%4];"
                 : "=r"(r[0]), "=r"(r[1]), "=r"(r[2]), "=r"(r[3]) : "r"(addr));
}
__device__ __forceinline__ void mma_bf16(float* c, const uint32_t* a,
                                         uint32_t b0, uint32_t b1) {
    asm volatile(
        "mma.sync.aligned.m16n8k16.row.col.f32.bf16.bf16.f32 "
        "{%0,%1,%2,%3}, {%4,%5,%6,%7}, {%8,%9}, {%0,%1,%2,%3};"
        : "+f"(c[0]), "+f"(c[1]), "+f"(c[2]), "+f"(c[3])
        : "r"(a[0]), "r"(a[1]), "r"(a[2]), "r"(a[3]), "r"(b0), "r"(b1));
}
__device__ __forceinline__ void mma_f16(float* c, const uint32_t* a,
                                        uint32_t b0, uint32_t b1) {
    asm volatile(
        "mma.sync.aligned.m16n8k16.row.col.f32.f16.f16.f32 "
        "{%0,%1,%2,%3}, {%4,%5,%6,%7}, {%8,%9}, {%0,%1,%2,%3};"
        : "+f"(c[0]), "+f"(c[1]), "+f"(c[2]), "+f"(c[3])
        : "r"(a[0]), "r"(a[1]), "r"(a[2]), "r"(a[3]), "r"(b0), "r"(b1));
}
__device__ __forceinline__ uint32_t pack_bf16(float lo, float hi) {
    __nv_bfloat162 h2 = __floats2bfloat162_rn(lo, hi);
    return *reinterpret_cast<uint32_t*>(&h2);
}
__device__ __forceinline__ float ex2(float x) {
    float y;
    asm("ex2.approx.ftz.f32 %0, %1;" : "=f"(y) : "f"(x));
    return y;
}
// pack (lo,hi) floats to f16x2 and take 2^x elementwise
__device__ __forceinline__ uint32_t exp2_f16x2(float hi, float lo) {
    uint32_t h, r;
    asm("cvt.rn.f16x2.f32 %0, %1, %2;" : "=r"(h) : "f"(hi), "f"(lo));
    asm("ex2.approx.f16x2 %0, %1;" : "=r"(r) : "r"(h));
    return r;
}
__device__ __forceinline__ void cp_async16(uint32_t saddr, const void* gptr) {
    asm volatile("cp.async.cg.shared.global [%0], [%1], 16;" :: "r"(saddr), "l"(gptr));
}
__device__ __forceinline__ void cp_commit() {
    asm volatile("cp.async.commit_group;");
}
template <int N> __device__ __forceinline__ void cp_wait() {
    asm volatile("cp.async.wait_group %0;" :: "n"(N));
}

// ---------------- fused fp32 -> bf16 weight conversion ----------------------
struct F2B { const float* s[6]; bf16* d[6]; };

__global__ void f2b_all_k(F2B t) {
    int bid = blockIdx.x;
    int seg, base;
    if (bid < 576) { seg = bid / 144; base = bid % 144; }
    else { seg = 4 + (bid - 576) / 576; base = (bid - 576) % 576; }
    int i = base * 256 + threadIdx.x;
    float4 v = ((const float4*)t.s[seg])[i];
    uint32_t pk[2] = {pack_bf16(v.x, v.y), pack_bf16(v.z, v.w)};
    ((uint2*)t.d[seg])[i] = *(uint2*)pk;
}

// ---------------- cond projections ------------------------------------------
struct CondW { const float* w[6]; const float* b[6]; };

__global__ void cond_proj_k(const float* __restrict__ cond, CondW P,
                            float* __restrict__ mod) {
    int proj = blockIdx.x >> 2;
    int bb   = blockIdx.x & 3;
    __shared__ float cs[E];
    int t = threadIdx.x;
    cs[t] = cond[bb * E + t];
    __syncthreads();
    const float* W = P.w[proj];
    float acc = P.b[proj][t];
#pragma unroll 4
    for (int kk = 0; kk < E; ++kk) acc = fmaf(cs[kk], W[kk * E + t], acc);
    mod[(proj * BATCH + bb) * E + t] = acc;
}

// ---------------- LayerNorm + AdaLN modulate (bf16 out) ---------------------
__global__ void __launch_bounds__(128)
ln_mod_k(const float* __restrict__ in,
         const float* __restrict__ lnw, const float* __restrict__ lnb,
         const float* __restrict__ gamma, const float* __restrict__ beta,
         bf16* __restrict__ out) {
    int row = blockIdx.x, t = threadIdx.x;
    int bb = row >> 12;
    const float* xr = in + (size_t)row * E;
    float v0 = xr[t], v1 = xr[t + 128], v2 = xr[t + 256];
    float s  = v0 + v1 + v2;
    float sq = v0 * v0 + v1 * v1 + v2 * v2;
#pragma unroll
    for (int off = 16; off; off >>= 1) {
        s  += __shfl_xor_sync(0xffffffffu, s,  off);
        sq += __shfl_xor_sync(0xffffffffu, sq, off);
    }
    __shared__ float rs[4], rq[4];
    int w = t >> 5;
    if ((t & 31) == 0) { rs[w] = s; rq[w] = sq; }
    __syncthreads();
    s  = rs[0] + rs[1] + rs[2] + rs[3];
    sq = rq[0] + rq[1] + rq[2] + rq[3];
    float mean = s * (1.0f / E);
    float var  = sq * (1.0f / E) - mean * mean;
    float rstd = rsqrtf(var + 1e-5f);
    bf16* orow = out + (size_t)row * E;
    const float* g  = gamma + bb * E;
    const float* be = beta  + bb * E;
    float vv[3] = {v0, v1, v2};
#pragma unroll
    for (int i = 0; i < 3; ++i) {
        int e = t + i * 128;
        float val = (vv[i] - mean) * rstd * lnw[e] + lnb[e];
        orow[e] = __float2bfloat16(fmaf(val, g[e], val + be[e]));
    }
}

// ---------------- bf16 tensor-core GEMM, 3-stage cp.async ring --------------
// EPI 0: q(bf16,*scale)/k(bf16)/v(fp16) via gridDim.z
// EPI 1: f32 out, res + C*alpha            (wo)
// EPI 2: bf16 out, relu(C + bias)          (ff1)
// EPI 3: f32 out, res + (C+bias)*alpha     (ff2 -> final)
#define ASTR 40
#define BSTR 136
#define GEMM_SMEM ((3 * 128 * ASTR + 3 * 32 * BSTR) * 2)

template <int EPI>
__global__ void __launch_bounds__(256, 2)
gemm_bf16_k(const bf16* __restrict__ A, const bf16* __restrict__ W,
            const float* __restrict__ bias, const float* __restrict__ alpha,
            const float* __restrict__ res, void* __restrict__ Cv,
            int M, int N, int K, float scale,
            const bf16* W2, const bf16* W3, void* C2, void* C3) {
    extern __shared__ char dynsmem[];
    bf16* As = (bf16*)dynsmem;                                  // [3][128*ASTR]
    bf16* Bs = (bf16*)(dynsmem + 3 * 128 * ASTR * 2);           // [3][32*BSTR]

    int zsel = 0;
    if (EPI == 0) {
        zsel = blockIdx.z;
        if (zsel == 1) { W = W2; Cv = C2; }
        else if (zsel == 2) { W = W3; Cv = C3; }
    }

    const int tid = threadIdx.x;
    const int lane = tid & 31, wid = tid >> 5;
    const int bm = blockIdx.y * 128;
    const int bn = blockIdx.x * 128;
    const int warp_m = wid >> 2, warp_n = wid & 3;

    const int a_row = tid >> 2, a_col = (tid & 3) * 8;
    const int b_row = tid >> 4, b_col = (tid & 15) * 8;
    const bf16* Abase = A + (size_t)(bm + a_row) * K + a_col;
    const bf16* Wbase = W + (size_t)b_row * N + bn + b_col;

    const int nk = K / 32;
    auto load_tile = [&](int st, int kb) {
        bf16* Ast = As + st * 128 * ASTR;
        bf16* Bst = Bs + st * 32 * BSTR;
        const bf16* Ab = Abase + kb * 32;
        cp_async16(sptr(&Ast[a_row * ASTR + a_col]), Ab);
        cp_async16(sptr(&Ast[(a_row + 64) * ASTR + a_col]), Ab + (size_t)64 * K);
        const bf16* Bb = Wbase + (size_t)(kb * 32) * N;
        cp_async16(sptr(&Bst[b_row * BSTR + b_col]), Bb);
        cp_async16(sptr(&Bst[(b_row + 16) * BSTR + b_col]), Bb + (size_t)16 * N);
        cp_commit();
    };

    load_tile(0, 0);
    if (nk > 1) load_tile(1, 1);

    float acc[4][4][4] = {};
    const int lrow = lane & 15, lcol = (lane >> 4) * 8;
    const int tb_row = (lane & 7) + ((lane & 8) ? 8 : 0);
    const int tb_col = (lane & 16) ? 8 : 0;

    int st = 0;
    for (int kb = 0; kb < nk; ++kb) {
        if (kb + 1 < nk) cp_wait<1>(); else cp_wait<0>();
        __syncthreads();
        if (kb + 2 < nk) {
            int nst = st + 2; if (nst >= 3) nst -= 3;
            load_tile(nst, kb + 2);
        }
        const bf16* Ast = As + st * 128 * ASTR;
        const bf16* Bst = Bs + st * 32 * BSTR;
#pragma unroll
        for (int ks = 0; ks < 2; ++ks) {
            uint32_t af[4][4];
#pragma unroll
            for (int mi = 0; mi < 4; ++mi)
                ldsm_x4(af[mi], sptr(&Ast[(warp_m * 64 + mi * 16 + lrow) * ASTR + ks * 16 + lcol]));
            uint32_t bf_[2][4];
#pragma unroll
            for (int ni2 = 0; ni2 < 2; ++ni2)
                ldsm_x4_t(bf_[ni2], sptr(&Bst[(ks * 16 + tb_row) * BSTR + warp_n * 32 + ni2 * 16 + tb_col]));
#pragma unroll
            for (int mi = 0; mi < 4; ++mi) {
#pragma unroll
                for (int ni2 = 0; ni2 < 2; ++ni2) {
                    mma_bf16(acc[mi][ni2 * 2],     af[mi], bf_[ni2][0], bf_[ni2][1]);
                    mma_bf16(acc[mi][ni2 * 2 + 1], af[mi], bf_[ni2][2], bf_[ni2][3]);
                }
            }
        }
        if (++st == 3) st = 0;
    }

    // epilogue
#pragma unroll
    for (int mi = 0; mi < 4; ++mi) {
#pragma unroll
        for (int rr = 0; rr < 2; ++rr) {
            int row = bm + warp_m * 64 + mi * 16 + (lane >> 2) + rr * 8;
            int bIdx = row >> 12;
            size_t rowoff = (size_t)row * N;
#pragma unroll
            for (int ni = 0; ni < 4; ++ni) {
                int col = bn + warp_n * 32 + ni * 8 + (lane & 3) * 2;
                float c0 = acc[mi][ni][rr * 2], c1 = acc[mi][ni][rr * 2 + 1];
                if (EPI == 0) {
                    if (zsel == 2) {
                        __half2 hv = __floats2half2_rn(c0, c1);
                        *(uint32_t*)((__half*)Cv + rowoff + col) = *(uint32_t*)&hv;
                    } else {
                        *(uint32_t*)((bf16*)Cv + rowoff + col) = pack_bf16(c0 * scale, c1 * scale);
                    }
                } else if (EPI == 2) {
                    float t0 = fmaxf(c0 + bias[col], 0.0f);
                    float t1 = fmaxf(c1 + bias[col + 1], 0.0f);
                    *(uint32_t*)((bf16*)Cv + rowoff + col) = pack_bf16(t0, t1);
                } else if (EPI == 1) {
                    float2 r = *(const float2*)(res + rowoff + col);
                    float a0f = alpha[bIdx * E + col], a1f = alpha[bIdx * E + col + 1];
                    *(float2*)((float*)Cv + rowoff + col) =
                        make_float2(r.x + c0 * a0f, r.y + c1 * a1f);
                } else {  // EPI == 3
                    float2 r = *(const float2*)(res + rowoff + col);
                    float a0f = alpha[bIdx * E + col], a1f = alpha[bIdx * E + col + 1];
                    *(float2*)((float*)Cv + rowoff + col) =
                        make_float2(r.x + (c0 + bias[col]) * a0f,
                                    r.y + (c1 + bias[col + 1]) * a1f);
                }
            }
        }
    }
}

// ---------------- flash attention: bf16 QK, f16 PV, 3-stage ring ------------
// block = 256 threads (8 warps), Q tile 128 rows, KV tiles 64 keys.
// Scores in log2 domain; softmax via ex2.approx.f16x2; P row-sums via mma.
#define KSTRIDE 72
#define ATT_SMEM (3 * 64 * KSTRIDE * 2 * 2)

__global__ void __launch_bounds__(256, 2)
attn_mma_k(const bf16* __restrict__ q, const bf16* __restrict__ k,
           const __half* __restrict__ v, bf16* __restrict__ out) {
    extern __shared__ char dynsmem[];
    bf16*   Ks = (bf16*)dynsmem;                                // [3][64*KSTRIDE]
    __half* Vs = (__half*)(dynsmem + 3 * 64 * KSTRIDE * 2);     // [3][64*KSTRIDE]

    const int tid = threadIdx.x;
    const int lane = tid & 31, w = tid >> 5;
    const int bh = blockIdx.y;
    const int b = bh / NH, h = bh % NH;
    const int q0 = blockIdx.x * 128;

    const int kv_row = tid >> 3;            // 0..31
    const int kv_col = (tid & 7) * 8;

    // ---- stage Q tile (128 rows) through Ks stages 0/1, ldmatrix to regs ----
#pragma unroll
    for (int p = 0; p < 4; ++p) {
        int row = kv_row + p * 32;
        bf16* dst = (row < 64) ? &Ks[row * KSTRIDE + kv_col]
                               : &Ks[64 * KSTRIDE + (row - 64) * KSTRIDE + kv_col];
        *(uint4*)dst = *(const uint4*)(q + ((size_t)(b * S + q0 + row)) * E + h * HD + kv_col);
    }
    __syncthreads();

    uint32_t a_q[4][4];
    {
        int lrow = lane & 15, lcol = (lane >> 4) * 8;
        const bf16* base = &Ks[((w < 4 ? w * 16 : 64 + (w - 4) * 16) + lrow) * KSTRIDE];
#pragma unroll
        for (int kc = 0; kc < 4; ++kc)
            ldsm_x4(a_q[kc], sptr(base + kc * 16 + lcol));
    }
    __syncthreads();    // Q reads complete before cp.async overwrites Ks

    const bf16*   kbase = k + ((size_t)(b * S) + kv_row) * E + h * HD + kv_col;
    const __half* vbase = v + ((size_t)(b * S) + kv_row) * E + h * HD + kv_col;
    auto load_kv = [&](int st, int kt) {
        bf16*   Kst = Ks + st * 64 * KSTRIDE;
        __half* Vst = Vs + st * 64 * KSTRIDE;
        const bf16*   kp = kbase + (size_t)(kt * 64) * E;
        const __half* vp = vbase + (size_t)(kt * 64) * E;
        cp_async16(sptr(&Kst[kv_row * KSTRIDE + kv_col]), kp);
        cp_async16(sptr(&Kst[(kv_row + 32) * KSTRIDE + kv_col]), kp + (size_t)32 * E);
        cp_async16(sptr(&Vst[kv_row * KSTRIDE + kv_col]), vp);
        cp_async16(sptr(&Vst[(kv_row + 32) * KSTRIDE + kv_col]), vp + (size_t)32 * E);
        cp_commit();
    };
    load_kv(0, 0);
    load_kv(1, 1);

    float mr0 = -1e30f, mr1 = -1e30f, l0 = 0.0f, l1 = 0.0f;
    float o[8][4] = {};

    const int kb_row = (lane & 7) + ((lane & 16) ? 8 : 0);
    const int kb_col = (lane & 8) ? 8 : 0;
    const int vb_row = (lane & 7) + ((lane & 8) ? 8 : 0);
    const int vb_col = (lane & 16) ? 8 : 0;
    const uint32_t ONES = 0x3C003C00u;   // f16x2 {1,1}

    const int nt = S / 64;
    int st = 0;
    for (int kt = 0; kt < nt; ++kt) {
        if (kt + 1 < nt) cp_wait<1>(); else cp_wait<0>();
        __syncthreads();
        if (kt + 2 < nt) {
            int nst = st + 2; if (nst >= 3) nst -= 3;
            load_kv(nst, kt + 2);
        }
        const bf16*   Kst = Ks + st * 64 * KSTRIDE;
        const __half* Vst = Vs + st * 64 * KSTRIDE;

        // ---- S = Q K^T (log2 domain) ----
        float s[8][4] = {};
#pragma unroll
        for (int kc = 0; kc < 4; ++kc) {
#pragma unroll
            for (int nb2 = 0; nb2 < 4; ++nb2) {
                uint32_t bb[4];
                ldsm_x4(bb, sptr(&Kst[(nb2 * 16 + kb_row) * KSTRIDE + kc * 16 + kb_col]));
                mma_bf16(s[nb2 * 2],     a_q[kc], bb[0], bb[1]);
                mma_bf16(s[nb2 * 2 + 1], a_q[kc], bb[2], bb[3]);
            }
        }

        // ---- online softmax (base-2, f16x2) ----
        float mx0 = -1e30f, mx1 = -1e30f;
#pragma unroll
        for (int j = 0; j < 8; ++j) {
            mx0 = fmaxf(mx0, fmaxf(s[j][0], s[j][1]));
            mx1 = fmaxf(mx1, fmaxf(s[j][2], s[j][3]));
        }
        mx0 = fmaxf(mx0, __shfl_xor_sync(0xffffffffu, mx0, 1));
        mx0 = fmaxf(mx0, __shfl_xor_sync(0xffffffffu, mx0, 2));
        mx1 = fmaxf(mx1, __shfl_xor_sync(0xffffffffu, mx1, 1));
        mx1 = fmaxf(mx1, __shfl_xor_sync(0xffffffffu, mx1, 2));
        float mn0 = fmaxf(mr0, mx0), mn1 = fmaxf(mr1, mx1);
        float c0 = ex2(mr0 - mn0), c1 = ex2(mr1 - mn1);

        uint32_t pA[8], pB[8];
#pragma unroll
        for (int j = 0; j < 8; ++j) {
            pA[j] = exp2_f16x2(s[j][1] - mn0, s[j][0] - mn0);
            pB[j] = exp2_f16x2(s[j][3] - mn1, s[j][2] - mn1);
        }
#pragma unroll
        for (int j = 0; j < 8; ++j) {
            o[j][0] *= c0; o[j][1] *= c0;
            o[j][2] *= c1; o[j][3] *= c1;
        }
        mr0 = mn0; mr1 = mn1;

        // ---- O += P V ; row-sums of P via ones-mma ----
        float ls[4] = {0.0f, 0.0f, 0.0f, 0.0f};
#pragma unroll
        for (int kc = 0; kc < 4; ++kc) {
            uint32_t ap[4] = {pA[2 * kc], pB[2 * kc], pA[2 * kc + 1], pB[2 * kc + 1]};
            mma_f16(ls, ap, ONES, ONES);
#pragma unroll
            for (int nb2 = 0; nb2 < 4; ++nb2) {
                uint32_t bb[4];
                ldsm_x4_t(bb, sptr(&Vst[(kc * 16 + vb_row) * KSTRIDE + nb2 * 16 + vb_col]));
                mma_f16(o[nb2 * 2],     ap, bb[0], bb[1]);
                mma_f16(o[nb2 * 2 + 1], ap, bb[2], bb[3]);
            }
        }
        l0 = l0 * c0 + ls[0];
        l1 = l1 * c1 + ls[2];
        if (++st == 3) st = 0;
    }

    // ---- epilogue (bf16 out) ----
    float i0 = 1.0f / l0, i1 = 1.0f / l1;
    int row0 = q0 + w * 16 + (lane >> 2);
    int colb = h * HD + (lane & 3) * 2;
    bf16* out0 = out + ((size_t)(b * S + row0)) * E + colb;
    bf16* out1 = out0 + 8 * (size_t)E;
#pragma unroll
    for (int j = 0; j < 8; ++j) {
        *(uint32_t*)(out0 + j * 8) = pack_bf16(o[j][0] * i0, o[j][1] * i0);
        *(uint32_t*)(out1 + j * 8) = pack_bf16(o[j][2] * i1, o[j][3] * i1);
    }
}

// ---------------- launcher ---------------------------------------------------
extern "C" void kernel_launch(void* const* d_in, const int* in_sizes, int n_in,
                              void* d_out, int out_size) {
    const float* x    = (const float*)d_in[0];
    const float* cond = (const float*)d_in[1];
    const float* ln1w = (const float*)d_in[14];
    const float* ln1b = (const float*)d_in[15];
    const float* ln2w = (const float*)d_in[16];
    const float* ln2b = (const float*)d_in[17];
    const float* ff1b = (const float*)d_in[23];
    const float* ff2b = (const float*)d_in[25];

    float *mod, *y;
    bf16 *ymod, *zmod, *qb, *kb, *att, *hb;
    __half* vb;
    bf16 *wqb, *wkb, *wvb, *wob, *ff1w_, *ff2w_;
    cudaGetSymbolAddress((void**)&mod,   g_mod);
    cudaGetSymbolAddress((void**)&ymod,  g_ymod);
    cudaGetSymbolAddress((void**)&zmod,  g_zmod);
    cudaGetSymbolAddress((void**)&qb,    g_q);
    cudaGetSymbolAddress((void**)&kb,    g_k);
    cudaGetSymbolAddress((void**)&vb,    g_v);
    cudaGetSymbolAddress((void**)&att,   g_att);
    cudaGetSymbolAddress((void**)&hb,    g_h);
    cudaGetSymbolAddress((void**)&y,     g_y);
    cudaGetSymbolAddress((void**)&wqb,   g_wq);
    cudaGetSymbolAddress((void**)&wkb,   g_wk);
    cudaGetSymbolAddress((void**)&wvb,   g_wv);
    cudaGetSymbolAddress((void**)&wob,   g_wo);
    cudaGetSymbolAddress((void**)&ff1w_, g_ff1);
    cudaGetSymbolAddress((void**)&ff2w_, g_ff2);

    // dynamic smem opt-in (>48KB)
    cudaFuncSetAttribute(gemm_bf16_k<0>, cudaFuncAttributeMaxDynamicSharedMemorySize, GEMM_SMEM);
    cudaFuncSetAttribute(gemm_bf16_k<1>, cudaFuncAttributeMaxDynamicSharedMemorySize, GEMM_SMEM);
    cudaFuncSetAttribute(gemm_bf16_k<2>, cudaFuncAttributeMaxDynamicSharedMemorySize, GEMM_SMEM);
    cudaFuncSetAttribute(gemm_bf16_k<3>, cudaFuncAttributeMaxDynamicSharedMemorySize, GEMM_SMEM);
    cudaFuncSetAttribute(attn_mma_k,     cudaFuncAttributeMaxDynamicSharedMemorySize, ATT_SMEM);

    CondW P;
    P.w[0] = (const float*)d_in[2];  P.b[0] = (const float*)d_in[3];
    P.w[1] = (const float*)d_in[4];  P.b[1] = (const float*)d_in[5];
    P.w[2] = (const float*)d_in[6];  P.b[2] = (const float*)d_in[7];
    P.w[3] = (const float*)d_in[8];  P.b[3] = (const float*)d_in[9];
    P.w[4] = (const float*)d_in[10]; P.b[4] = (const float*)d_in[11];
    P.w[5] = (const float*)d_in[12]; P.b[5] = (const float*)d_in[13];

    const float* gamma1 = mod + 0 * BATCH * E;
    const float* beta1  = mod + 1 * BATCH * E;
    const float* alpha1 = mod + 2 * BATCH * E;
    const float* gamma2 = mod + 3 * BATCH * E;
    const float* beta2  = mod + 4 * BATCH * E;
    const float* alpha2 = mod + 5 * BATCH * E;

    F2B T;
    T.s[0] = (const float*)d_in[18]; T.d[0] = wqb;
    T.s[1] = (const float*)d_in[19]; T.d[1] = wkb;
    T.s[2] = (const float*)d_in[20]; T.d[2] = wvb;
    T.s[3] = (const float*)d_in[21]; T.d[3] = wob;
    T.s[4] = (const float*)d_in[22]; T.d[4] = ff1w_;
    T.s[5] = (const float*)d_in[24]; T.d[5] = ff2w_;
    f2b_all_k<<<1728, 256>>>(T);

    cond_proj_k<<<24, E>>>(cond, P, mod);
    ln_mod_k<<<NROWS, 128>>>(x, ln1w, ln1b, gamma1, beta1, ymod);

    // fused QKV; q scaled by 0.125 * log2(e) for base-2 softmax
    dim3 gQKV(E / 128, NROWS / 128, 3);
    gemm_bf16_k<0><<<gQKV, 256, GEMM_SMEM>>>(ymod, wqb, nullptr, nullptr, nullptr, qb,
                                             NROWS, E, E, 0.18033688f, wkb, wvb, kb, vb);

    attn_mma_k<<<dim3(S / 128, BATCH * NH), 256, ATT_SMEM>>>(qb, kb, vb, att);

    dim3 gE(E / 128, NROWS / 128);
    gemm_bf16_k<1><<<gE, 256, GEMM_SMEM>>>(att, wob, nullptr, alpha1, x, y,
                                           NROWS, E, E, 1.0f, nullptr, nullptr, nullptr, nullptr);

    ln_mod_k<<<NROWS, 128>>>(y, ln2w, ln2b, gamma2, beta2, zmod);

    dim3 gH(HID / 128, NROWS / 128);
    gemm_bf16_k<2><<<gH, 256, GEMM_SMEM>>>(zmod, ff1w_, ff1b, nullptr, nullptr, hb,
                                           NROWS, HID, E, 1.0f, nullptr, nullptr, nullptr, nullptr);
    gemm_bf16_k<3><<<gE, 256, GEMM_SMEM>>>(hb, ff2w_, ff2b, alpha2, y, d_out,
                                           NROWS, E, HID, 1.0f, nullptr, nullptr, nullptr, nullptr);
}

// round 6
// speedup vs baseline: 15.1302x; 1.0004x over previous
#include <cuda_runtime.h>
#include <cuda_bf16.h>
#include <cuda_fp16.h>
#include <cstdint>
#include <cstddef>

#define E 384
#define S 4096
#define BATCH 4
#define NROWS (BATCH * S)      // 16384
#define HID 1536
#define NH 6
#define HD 64

typedef __nv_bfloat16 bf16;

// ---------------- scratch (device globals — no runtime allocation) ----------
__device__ float  g_mod[6 * BATCH * E];
__device__ bf16   g_ymod[(size_t)NROWS * E];
__device__ bf16   g_zmod[(size_t)NROWS * E];
__device__ bf16   g_q[(size_t)NROWS * E];
__device__ bf16   g_k[(size_t)NROWS * E];
__device__ __half g_v[(size_t)NROWS * E];
__device__ bf16   g_att[(size_t)NROWS * E];
__device__ bf16   g_h[(size_t)NROWS * HID];
__device__ float  g_y[(size_t)NROWS * E];
__device__ bf16 g_wq[E * E];
__device__ bf16 g_wk[E * E];
__device__ bf16 g_wv[E * E];
__device__ bf16 g_wo[E * E];
__device__ bf16 g_ff1[E * HID];
__device__ bf16 g_ff2[HID * E];

// ---------------- small helpers --------------------------------------------
__device__ __forceinline__ uint32_t sptr(const void* p) {
    return (uint32_t)__cvta_generic_to_shared(p);
}
__device__ __forceinline__ void ldsm_x4(uint32_t* r, uint32_t addr) {
    asm volatile("ldmatrix.sync.aligned.m8n8.x4.shared.b16 {%0,%1,%2,%3}, [%4];"
                 : "=r"(r[0]), "=r"(r[1]), "=r"(r[2]), "=r"(r[3]) : "r"(addr));
}
__device__ __forceinline__ void ldsm_x4_t(uint32_t* r, uint32_t addr) {
    asm volatile("ldmatrix.sync.aligned.m8n8.x4.trans.shared.b16 {%0,%1,%2,%3}, [%4];"
                 : "=r"(r[0]), "=r"(r[1]), "=r"(r[2]), "=r"(r[3]) : "r"(addr));
}
__device__ __forceinline__ void mma_bf16(float* c, const uint32_t* a,
                                         uint32_t b0, uint32_t b1) {
    asm volatile(
        "mma.sync.aligned.m16n8k16.row.col.f32.bf16.bf16.f32 "
        "{%0,%1,%2,%3}, {%4,%5,%6,%7}, {%8,%9}, {%0,%1,%2,%3};"
        : "+f"(c[0]), "+f"(c[1]), "+f"(c[2]), "+f"(c[3])
        : "r"(a[0]), "r"(a[1]), "r"(a[2]), "r"(a[3]), "r"(b0), "r"(b1));
}
__device__ __forceinline__ void mma_f16(float* c, const uint32_t* a,
                                        uint32_t b0, uint32_t b1) {
    asm volatile(
        "mma.sync.aligned.m16n8k16.row.col.f32.f16.f16.f32 "
        "{%0,%1,%2,%3}, {%4,%5,%6,%7}, {%8,%9}, {%0,%1,%2,%3};"
        : "+f"(c[0]), "+f"(c[1]), "+f"(c[2]), "+f"(c[3])
        : "r"(a[0]), "r"(a[1]), "r"(a[2]), "r"(a[3]), "r"(b0), "r"(b1));
}
__device__ __forceinline__ uint32_t pack_bf16(float lo, float hi) {
    __nv_bfloat162 h2 = __floats2bfloat162_rn(lo, hi);
    return *reinterpret_cast<uint32_t*>(&h2);
}
__device__ __forceinline__ float ex2(float x) {
    float y;
    asm("ex2.approx.ftz.f32 %0, %1;" : "=f"(y) : "f"(x));
    return y;
}
// pack (lo,hi) floats to f16x2 and take 2^x elementwise
__device__ __forceinline__ uint32_t exp2_f16x2(float hi, float lo) {
    uint32_t h, r;
    asm("cvt.rn.f16x2.f32 %0, %1, %2;" : "=r"(h) : "f"(hi), "f"(lo));
    asm("ex2.approx.f16x2 %0, %1;" : "=r"(r) : "r"(h));
    return r;
}
__device__ __forceinline__ void cp_async16(uint32_t saddr, const void* gptr) {
    asm volatile("cp.async.cg.shared.global [%0], [%1], 16;" :: "r"(saddr), "l"(gptr));
}
__device__ __forceinline__ void cp_commit() {
    asm volatile("cp.async.commit_group;");
}
template <int N> __device__ __forceinline__ void cp_wait() {
    asm volatile("cp.async.wait_group %0;" :: "n"(N));
}

// ---------------- fused fp32 -> bf16 weight conversion ----------------------
struct F2B { const float* s[6]; bf16* d[6]; };

__global__ void f2b_all_k(F2B t) {
    int bid = blockIdx.x;
    int seg, base;
    if (bid < 576) { seg = bid / 144; base = bid % 144; }
    else { seg = 4 + (bid - 576) / 576; base = (bid - 576) % 576; }
    int i = base * 256 + threadIdx.x;
    float4 v = ((const float4*)t.s[seg])[i];
    uint32_t pk[2] = {pack_bf16(v.x, v.y), pack_bf16(v.z, v.w)};
    ((uint2*)t.d[seg])[i] = *(uint2*)pk;
}

// ---------------- cond projections ------------------------------------------
struct CondW { const float* w[6]; const float* b[6]; };

__global__ void cond_proj_k(const float* __restrict__ cond, CondW P,
                            float* __restrict__ mod) {
    int proj = blockIdx.x >> 2;
    int bb   = blockIdx.x & 3;
    __shared__ float cs[E];
    int t = threadIdx.x;
    cs[t] = cond[bb * E + t];
    __syncthreads();
    const float* W = P.w[proj];
    float acc = P.b[proj][t];
#pragma unroll 4
    for (int kk = 0; kk < E; ++kk) acc = fmaf(cs[kk], W[kk * E + t], acc);
    mod[(proj * BATCH + bb) * E + t] = acc;
}

// ---------------- LayerNorm + AdaLN modulate (bf16 out) ---------------------
__global__ void __launch_bounds__(128)
ln_mod_k(const float* __restrict__ in,
         const float* __restrict__ lnw, const float* __restrict__ lnb,
         const float* __restrict__ gamma, const float* __restrict__ beta,
         bf16* __restrict__ out) {
    int row = blockIdx.x, t = threadIdx.x;
    int bb = row >> 12;
    const float* xr = in + (size_t)row * E;
    float v0 = xr[t], v1 = xr[t + 128], v2 = xr[t + 256];
    float s  = v0 + v1 + v2;
    float sq = v0 * v0 + v1 * v1 + v2 * v2;
#pragma unroll
    for (int off = 16; off; off >>= 1) {
        s  += __shfl_xor_sync(0xffffffffu, s,  off);
        sq += __shfl_xor_sync(0xffffffffu, sq, off);
    }
    __shared__ float rs[4], rq[4];
    int w = t >> 5;
    if ((t & 31) == 0) { rs[w] = s; rq[w] = sq; }
    __syncthreads();
    s  = rs[0] + rs[1] + rs[2] + rs[3];
    sq = rq[0] + rq[1] + rq[2] + rq[3];
    float mean = s * (1.0f / E);
    float var  = sq * (1.0f / E) - mean * mean;
    float rstd = rsqrtf(var + 1e-5f);
    bf16* orow = out + (size_t)row * E;
    const float* g  = gamma + bb * E;
    const float* be = beta  + bb * E;
    float vv[3] = {v0, v1, v2};
#pragma unroll
    for (int i = 0; i < 3; ++i) {
        int e = t + i * 128;
        float val = (vv[i] - mean) * rstd * lnw[e] + lnb[e];
        orow[e] = __float2bfloat16(fmaf(val, g[e], val + be[e]));
    }
}

// ---------------- bf16 tensor-core GEMM, 3-stage cp.async ring --------------
// EPI 0: q(bf16,*scale)/k(bf16)/v(fp16) via gridDim.z
// EPI 1: f32 out, res + C*alpha            (wo)
// EPI 2: bf16 out, relu(C + bias)          (ff1)
// EPI 3: f32 out, res + (C+bias)*alpha     (ff2 -> final)
#define ASTR 40
#define BSTR 136
#define GEMM_SMEM ((3 * 128 * ASTR + 3 * 32 * BSTR) * 2)

template <int EPI>
__global__ void __launch_bounds__(256, 2)
gemm_bf16_k(const bf16* __restrict__ A, const bf16* __restrict__ W,
            const float* __restrict__ bias, const float* __restrict__ alpha,
            const float* __restrict__ res, void* __restrict__ Cv,
            int M, int N, int K, float scale,
            const bf16* W2, const bf16* W3, void* C2, void* C3) {
    extern __shared__ char dynsmem[];
    bf16* As = (bf16*)dynsmem;                                  // [3][128*ASTR]
    bf16* Bs = (bf16*)(dynsmem + 3 * 128 * ASTR * 2);           // [3][32*BSTR]

    int zsel = 0;
    if (EPI == 0) {
        zsel = blockIdx.z;
        if (zsel == 1) { W = W2; Cv = C2; }
        else if (zsel == 2) { W = W3; Cv = C3; }
    }

    const int tid = threadIdx.x;
    const int lane = tid & 31, wid = tid >> 5;
    const int bm = blockIdx.y * 128;
    const int bn = blockIdx.x * 128;
    const int warp_m = wid >> 2, warp_n = wid & 3;

    const int a_row = tid >> 2, a_col = (tid & 3) * 8;
    const int b_row = tid >> 4, b_col = (tid & 15) * 8;
    const bf16* Abase = A + (size_t)(bm + a_row) * K + a_col;
    const bf16* Wbase = W + (size_t)b_row * N + bn + b_col;

    const int nk = K / 32;
    auto load_tile = [&](int st, int kb) {
        bf16* Ast = As + st * 128 * ASTR;
        bf16* Bst = Bs + st * 32 * BSTR;
        const bf16* Ab = Abase + kb * 32;
        cp_async16(sptr(&Ast[a_row * ASTR + a_col]), Ab);
        cp_async16(sptr(&Ast[(a_row + 64) * ASTR + a_col]), Ab + (size_t)64 * K);
        const bf16* Bb = Wbase + (size_t)(kb * 32) * N;
        cp_async16(sptr(&Bst[b_row * BSTR + b_col]), Bb);
        cp_async16(sptr(&Bst[(b_row + 16) * BSTR + b_col]), Bb + (size_t)16 * N);
        cp_commit();
    };

    load_tile(0, 0);
    if (nk > 1) load_tile(1, 1);

    float acc[4][4][4] = {};
    const int lrow = lane & 15, lcol = (lane >> 4) * 8;
    const int tb_row = (lane & 7) + ((lane & 8) ? 8 : 0);
    const int tb_col = (lane & 16) ? 8 : 0;

    int st = 0;
    for (int kb = 0; kb < nk; ++kb) {
        if (kb + 1 < nk) cp_wait<1>(); else cp_wait<0>();
        __syncthreads();
        if (kb + 2 < nk) {
            int nst = st + 2; if (nst >= 3) nst -= 3;
            load_tile(nst, kb + 2);
        }
        const bf16* Ast = As + st * 128 * ASTR;
        const bf16* Bst = Bs + st * 32 * BSTR;
#pragma unroll
        for (int ks = 0; ks < 2; ++ks) {
            uint32_t af[4][4];
#pragma unroll
            for (int mi = 0; mi < 4; ++mi)
                ldsm_x4(af[mi], sptr(&Ast[(warp_m * 64 + mi * 16 + lrow) * ASTR + ks * 16 + lcol]));
            uint32_t bf_[2][4];
#pragma unroll
            for (int ni2 = 0; ni2 < 2; ++ni2)
                ldsm_x4_t(bf_[ni2], sptr(&Bst[(ks * 16 + tb_row) * BSTR + warp_n * 32 + ni2 * 16 + tb_col]));
#pragma unroll
            for (int mi = 0; mi < 4; ++mi) {
#pragma unroll
                for (int ni2 = 0; ni2 < 2; ++ni2) {
                    mma_bf16(acc[mi][ni2 * 2],     af[mi], bf_[ni2][0], bf_[ni2][1]);
                    mma_bf16(acc[mi][ni2 * 2 + 1], af[mi], bf_[ni2][2], bf_[ni2][3]);
                }
            }
        }
        if (++st == 3) st = 0;
    }

    // epilogue
#pragma unroll
    for (int mi = 0; mi < 4; ++mi) {
#pragma unroll
        for (int rr = 0; rr < 2; ++rr) {
            int row = bm + warp_m * 64 + mi * 16 + (lane >> 2) + rr * 8;
            int bIdx = row >> 12;
            size_t rowoff = (size_t)row * N;
#pragma unroll
            for (int ni = 0; ni < 4; ++ni) {
                int col = bn + warp_n * 32 + ni * 8 + (lane & 3) * 2;
                float c0 = acc[mi][ni][rr * 2], c1 = acc[mi][ni][rr * 2 + 1];
                if (EPI == 0) {
                    if (zsel == 2) {
                        __half2 hv = __floats2half2_rn(c0, c1);
                        *(uint32_t*)((__half*)Cv + rowoff + col) = *(uint32_t*)&hv;
                    } else {
                        *(uint32_t*)((bf16*)Cv + rowoff + col) = pack_bf16(c0 * scale, c1 * scale);
                    }
                } else if (EPI == 2) {
                    float t0 = fmaxf(c0 + bias[col], 0.0f);
                    float t1 = fmaxf(c1 + bias[col + 1], 0.0f);
                    *(uint32_t*)((bf16*)Cv + rowoff + col) = pack_bf16(t0, t1);
                } else if (EPI == 1) {
                    float2 r = *(const float2*)(res + rowoff + col);
                    float a0f = alpha[bIdx * E + col], a1f = alpha[bIdx * E + col + 1];
                    *(float2*)((float*)Cv + rowoff + col) =
                        make_float2(r.x + c0 * a0f, r.y + c1 * a1f);
                } else {  // EPI == 3
                    float2 r = *(const float2*)(res + rowoff + col);
                    float a0f = alpha[bIdx * E + col], a1f = alpha[bIdx * E + col + 1];
                    *(float2*)((float*)Cv + rowoff + col) =
                        make_float2(r.x + (c0 + bias[col]) * a0f,
                                    r.y + (c1 + bias[col + 1]) * a1f);
                }
            }
        }
    }
}

// ---------------- flash attention: bf16 QK, f16 PV, 3-stage ring ------------
// block = 256 threads (8 warps), Q tile 128 rows, KV tiles 64 keys.
// Scores in log2 domain; softmax via ex2.approx.f16x2; P row-sums via mma.
#define KSTRIDE 72
#define ATT_SMEM (3 * 64 * KSTRIDE * 2 * 2)

__global__ void __launch_bounds__(256, 2)
attn_mma_k(const bf16* __restrict__ q, const bf16* __restrict__ k,
           const __half* __restrict__ v, bf16* __restrict__ out) {
    extern __shared__ char dynsmem[];
    bf16*   Ks = (bf16*)dynsmem;                                // [3][64*KSTRIDE]
    __half* Vs = (__half*)(dynsmem + 3 * 64 * KSTRIDE * 2);     // [3][64*KSTRIDE]

    const int tid = threadIdx.x;
    const int lane = tid & 31, w = tid >> 5;
    const int bh = blockIdx.y;
    const int b = bh / NH, h = bh % NH;
    const int q0 = blockIdx.x * 128;

    const int kv_row = tid >> 3;            // 0..31
    const int kv_col = (tid & 7) * 8;

    // ---- stage Q tile (128 rows) through Ks stages 0/1, ldmatrix to regs ----
#pragma unroll
    for (int p = 0; p < 4; ++p) {
        int row = kv_row + p * 32;
        bf16* dst = (row < 64) ? &Ks[row * KSTRIDE + kv_col]
                               : &Ks[64 * KSTRIDE + (row - 64) * KSTRIDE + kv_col];
        *(uint4*)dst = *(const uint4*)(q + ((size_t)(b * S + q0 + row)) * E + h * HD + kv_col);
    }
    __syncthreads();

    uint32_t a_q[4][4];
    {
        int lrow = lane & 15, lcol = (lane >> 4) * 8;
        const bf16* base = &Ks[((w < 4 ? w * 16 : 64 + (w - 4) * 16) + lrow) * KSTRIDE];
#pragma unroll
        for (int kc = 0; kc < 4; ++kc)
            ldsm_x4(a_q[kc], sptr(base + kc * 16 + lcol));
    }
    __syncthreads();    // Q reads complete before cp.async overwrites Ks

    const bf16*   kbase = k + ((size_t)(b * S) + kv_row) * E + h * HD + kv_col;
    const __half* vbase = v + ((size_t)(b * S) + kv_row) * E + h * HD + kv_col;
    auto load_kv = [&](int st, int kt) {
        bf16*   Kst = Ks + st * 64 * KSTRIDE;
        __half* Vst = Vs + st * 64 * KSTRIDE;
        const bf16*   kp = kbase + (size_t)(kt * 64) * E;
        const __half* vp = vbase + (size_t)(kt * 64) * E;
        cp_async16(sptr(&Kst[kv_row * KSTRIDE + kv_col]), kp);
        cp_async16(sptr(&Kst[(kv_row + 32) * KSTRIDE + kv_col]), kp + (size_t)32 * E);
        cp_async16(sptr(&Vst[kv_row * KSTRIDE + kv_col]), vp);
        cp_async16(sptr(&Vst[(kv_row + 32) * KSTRIDE + kv_col]), vp + (size_t)32 * E);
        cp_commit();
    };
    load_kv(0, 0);
    load_kv(1, 1);

    float mr0 = -1e30f, mr1 = -1e30f, l0 = 0.0f, l1 = 0.0f;
    float o[8][4] = {};

    const int kb_row = (lane & 7) + ((lane & 16) ? 8 : 0);
    const int kb_col = (lane & 8) ? 8 : 0;
    const int vb_row = (lane & 7) + ((lane & 8) ? 8 : 0);
    const int vb_col = (lane & 16) ? 8 : 0;
    const uint32_t ONES = 0x3C003C00u;   // f16x2 {1,1}

    const int nt = S / 64;
    int st = 0;
    for (int kt = 0; kt < nt; ++kt) {
        if (kt + 1 < nt) cp_wait<1>(); else cp_wait<0>();
        __syncthreads();
        if (kt + 2 < nt) {
            int nst = st + 2; if (nst >= 3) nst -= 3;
            load_kv(nst, kt + 2);
        }
        const bf16*   Kst = Ks + st * 64 * KSTRIDE;
        const __half* Vst = Vs + st * 64 * KSTRIDE;

        // ---- S = Q K^T (log2 domain) ----
        float s[8][4] = {};
#pragma unroll
        for (int kc = 0; kc < 4; ++kc) {
#pragma unroll
            for (int nb2 = 0; nb2 < 4; ++nb2) {
                uint32_t bb[4];
                ldsm_x4(bb, sptr(&Kst[(nb2 * 16 + kb_row) * KSTRIDE + kc * 16 + kb_col]));
                mma_bf16(s[nb2 * 2],     a_q[kc], bb[0], bb[1]);
                mma_bf16(s[nb2 * 2 + 1], a_q[kc], bb[2], bb[3]);
            }
        }

        // ---- online softmax (base-2, f16x2) ----
        float mx0 = -1e30f, mx1 = -1e30f;
#pragma unroll
        for (int j = 0; j < 8; ++j) {
            mx0 = fmaxf(mx0, fmaxf(s[j][0], s[j][1]));
            mx1 = fmaxf(mx1, fmaxf(s[j][2], s[j][3]));
        }
        mx0 = fmaxf(mx0, __shfl_xor_sync(0xffffffffu, mx0, 1));
        mx0 = fmaxf(mx0, __shfl_xor_sync(0xffffffffu, mx0, 2));
        mx1 = fmaxf(mx1, __shfl_xor_sync(0xffffffffu, mx1, 1));
        mx1 = fmaxf(mx1, __shfl_xor_sync(0xffffffffu, mx1, 2));
        float mn0 = fmaxf(mr0, mx0), mn1 = fmaxf(mr1, mx1);
        float c0 = ex2(mr0 - mn0), c1 = ex2(mr1 - mn1);

        uint32_t pA[8], pB[8];
#pragma unroll
        for (int j = 0; j < 8; ++j) {
            pA[j] = exp2_f16x2(s[j][1] - mn0, s[j][0] - mn0);
            pB[j] = exp2_f16x2(s[j][3] - mn1, s[j][2] - mn1);
        }
#pragma unroll
        for (int j = 0; j < 8; ++j) {
            o[j][0] *= c0; o[j][1] *= c0;
            o[j][2] *= c1; o[j][3] *= c1;
        }
        mr0 = mn0; mr1 = mn1;

        // ---- O += P V ; row-sums of P via ones-mma ----
        float ls[4] = {0.0f, 0.0f, 0.0f, 0.0f};
#pragma unroll
        for (int kc = 0; kc < 4; ++kc) {
            uint32_t ap[4] = {pA[2 * kc], pB[2 * kc], pA[2 * kc + 1], pB[2 * kc + 1]};
            mma_f16(ls, ap, ONES, ONES);
#pragma unroll
            for (int nb2 = 0; nb2 < 4; ++nb2) {
                uint32_t bb[4];
                ldsm_x4_t(bb, sptr(&Vst[(kc * 16 + vb_row) * KSTRIDE + nb2 * 16 + vb_col]));
                mma_f16(o[nb2 * 2],     ap, bb[0], bb[1]);
                mma_f16(o[nb2 * 2 + 1], ap, bb[2], bb[3]);
            }
        }
        l0 = l0 * c0 + ls[0];
        l1 = l1 * c1 + ls[2];
        if (++st == 3) st = 0;
    }

    // ---- epilogue (bf16 out) ----
    float i0 = 1.0f / l0, i1 = 1.0f / l1;
    int row0 = q0 + w * 16 + (lane >> 2);
    int colb = h * HD + (lane & 3) * 2;
    bf16* out0 = out + ((size_t)(b * S + row0)) * E + colb;
    bf16* out1 = out0 + 8 * (size_t)E;
#pragma unroll
    for (int j = 0; j < 8; ++j) {
        *(uint32_t*)(out0 + j * 8) = pack_bf16(o[j][0] * i0, o[j][1] * i0);
        *(uint32_t*)(out1 + j * 8) = pack_bf16(o[j][2] * i1, o[j][3] * i1);
    }
}

// ---------------- launcher ---------------------------------------------------
extern "C" void kernel_launch(void* const* d_in, const int* in_sizes, int n_in,
                              void* d_out, int out_size) {
    const float* x    = (const float*)d_in[0];
    const float* cond = (const float*)d_in[1];
    const float* ln1w = (const float*)d_in[14];
    const float* ln1b = (const float*)d_in[15];
    const float* ln2w = (const float*)d_in[16];
    const float* ln2b = (const float*)d_in[17];
    const float* ff1b = (const float*)d_in[23];
    const float* ff2b = (const float*)d_in[25];

    float *mod, *y;
    bf16 *ymod, *zmod, *qb, *kb, *att, *hb;
    __half* vb;
    bf16 *wqb, *wkb, *wvb, *wob, *ff1w_, *ff2w_;
    cudaGetSymbolAddress((void**)&mod,   g_mod);
    cudaGetSymbolAddress((void**)&ymod,  g_ymod);
    cudaGetSymbolAddress((void**)&zmod,  g_zmod);
    cudaGetSymbolAddress((void**)&qb,    g_q);
    cudaGetSymbolAddress((void**)&kb,    g_k);
    cudaGetSymbolAddress((void**)&vb,    g_v);
    cudaGetSymbolAddress((void**)&att,   g_att);
    cudaGetSymbolAddress((void**)&hb,    g_h);
    cudaGetSymbolAddress((void**)&y,     g_y);
    cudaGetSymbolAddress((void**)&wqb,   g_wq);
    cudaGetSymbolAddress((void**)&wkb,   g_wk);
    cudaGetSymbolAddress((void**)&wvb,   g_wv);
    cudaGetSymbolAddress((void**)&wob,   g_wo);
    cudaGetSymbolAddress((void**)&ff1w_, g_ff1);
    cudaGetSymbolAddress((void**)&ff2w_, g_ff2);

    // dynamic smem opt-in (>48KB)
    cudaFuncSetAttribute(gemm_bf16_k<0>, cudaFuncAttributeMaxDynamicSharedMemorySize, GEMM_SMEM);
    cudaFuncSetAttribute(gemm_bf16_k<1>, cudaFuncAttributeMaxDynamicSharedMemorySize, GEMM_SMEM);
    cudaFuncSetAttribute(gemm_bf16_k<2>, cudaFuncAttributeMaxDynamicSharedMemorySize, GEMM_SMEM);
    cudaFuncSetAttribute(gemm_bf16_k<3>, cudaFuncAttributeMaxDynamicSharedMemorySize, GEMM_SMEM);
    cudaFuncSetAttribute(attn_mma_k,     cudaFuncAttributeMaxDynamicSharedMemorySize, ATT_SMEM);

    CondW P;
    P.w[0] = (const float*)d_in[2];  P.b[0] = (const float*)d_in[3];
    P.w[1] = (const float*)d_in[4];  P.b[1] = (const float*)d_in[5];
    P.w[2] = (const float*)d_in[6];  P.b[2] = (const float*)d_in[7];
    P.w[3] = (const float*)d_in[8];  P.b[3] = (const float*)d_in[9];
    P.w[4] = (const float*)d_in[10]; P.b[4] = (const float*)d_in[11];
    P.w[5] = (const float*)d_in[12]; P.b[5] = (const float*)d_in[13];

    const float* gamma1 = mod + 0 * BATCH * E;
    const float* beta1  = mod + 1 * BATCH * E;
    const float* alpha1 = mod + 2 * BATCH * E;
    const float* gamma2 = mod + 3 * BATCH * E;
    const float* beta2  = mod + 4 * BATCH * E;
    const float* alpha2 = mod + 5 * BATCH * E;

    F2B T;
    T.s[0] = (const float*)d_in[18]; T.d[0] = wqb;
    T.s[1] = (const float*)d_in[19]; T.d[1] = wkb;
    T.s[2] = (const float*)d_in[20]; T.d[2] = wvb;
    T.s[3] = (const float*)d_in[21]; T.d[3] = wob;
    T.s[4] = (const float*)d_in[22]; T.d[4] = ff1w_;
    T.s[5] = (const float*)d_in[24]; T.d[5] = ff2w_;
    f2b_all_k<<<1728, 256>>>(T);

    cond_proj_k<<<24, E>>>(cond, P, mod);
    ln_mod_k<<<NROWS, 128>>>(x, ln1w, ln1b, gamma1, beta1, ymod);

    // fused QKV; q scaled by 0.125 * log2(e) for base-2 softmax
    dim3 gQKV(E / 128, NROWS / 128, 3);
    gemm_bf16_k<0><<<gQKV, 256, GEMM_SMEM>>>(ymod, wqb, nullptr, nullptr, nullptr, qb,
                                             NROWS, E, E, 0.18033688f, wkb, wvb, kb, vb);

    attn_mma_k<<<dim3(S / 128, BATCH * NH), 256, ATT_SMEM>>>(qb, kb, vb, att);

    dim3 gE(E / 128, NROWS / 128);
    gemm_bf16_k<1><<<gE, 256, GEMM_SMEM>>>(att, wob, nullptr, alpha1, x, y,
                                           NROWS, E, E, 1.0f, nullptr, nullptr, nullptr, nullptr);

    ln_mod_k<<<NROWS, 128>>>(y, ln2w, ln2b, gamma2, beta2, zmod);

    dim3 gH(HID / 128, NROWS / 128);
    gemm_bf16_k<2><<<gH, 256, GEMM_SMEM>>>(zmod, ff1w_, ff1b, nullptr, nullptr, hb,
                                           NROWS, HID, E, 1.0f, nullptr, nullptr, nullptr, nullptr);
    gemm_bf16_k<3><<<gE, 256, GEMM_SMEM>>>(hb, ff2w_, ff2b, alpha2, y, d_out,
                                           NROWS, E, HID, 1.0f, nullptr, nullptr, nullptr, nullptr);
}